// round 10
// baseline (speedup 1.0000x reference)
#include <cuda_runtime.h>
#include <cuda_fp16.h>
#include <math.h>
#include <stdint.h>

#define HW    4096
#define CIN   512
#define COUT  256
#define BATCH 32

// ---- proj GEMM tiling (fp16 MMA, BM=256 / A-from-L2) ----
#define BM 256
#define BN 128
#define BK 16
#define NKT (CIN / BK)          // 32
#define NSTB 8
#define NTHREADS 256
#define NXT (HW / BN)           // 32 n-tiles
#define B_STRIDE 132                          // fp32 per B stage row (2tg-row conflict-free)
#define B_STAGE_BYTES (BK * B_STRIDE * 4)     // 8448
#define PBUF_OFF (NSTB * B_STAGE_BYTES)       // 67584
#define GACC_OFF (PBUF_OFF + 128 * 4)         // 68096
#define SMEM_TOTAL (GACC_OFF + 512 * 4)       // 70144

// ---- attn smem layout (unchanged) ----
#define MS_STRIDE 260
#define LS_STRIDE 136
#define AT_MEMS_OFF 0
#define AT_LSM_OFF  (32 * MS_STRIDE * 4)
#define AT_STG_OFF  (AT_LSM_OFF + 32 * LS_STRIDE * 4)
#define AT_STAGE_BYTES (16 * LS_STRIDE * 4)
#define AT_SMEM_TOTAL (AT_STG_OFF + 4 * AT_STAGE_BYTES) // 85504

// ---------------- device scratch ----------------
__device__ uint32_t g_Wh2[COUT * CIN / 2];   // W packed half2, [COUT][256] u32
__device__ float g_part[NXT][BATCH][CIN];
__device__ float g_predsum[BATCH];
__device__ float g_pooled[BATCH * COUT];
__device__ float g_mem[BATCH * COUT];
__device__ int   g_ptr;

__device__ __forceinline__ float warp_sum(float v) {
#pragma unroll
    for (int o = 16; o; o >>= 1) v += __shfl_down_sync(0xffffffffu, v, o);
    return v;
}
__device__ __forceinline__ uint32_t smem_u32(const void* p) {
    uint32_t a;
    asm("{ .reg .u64 t; cvta.to.shared.u64 t, %1; cvt.u32.u64 %0, t; }" : "=r"(a) : "l"(p));
    return a;
}
__device__ __forceinline__ uint32_t f2tf32(float f) {
    uint32_t r;
    asm("cvt.rna.tf32.f32 %0, %1;" : "=r"(r) : "f"(f));
    return r;
}
__device__ __forceinline__ uint32_t pack_h2(float lo, float hi) {
    __half2 h = __floats2half2_rn(lo, hi);
    return *(uint32_t*)&h;
}
#define CP_ASYNC16(saddr, gaddr) \
    asm volatile("cp.async.cg.shared.global [%0], [%1], 16;" :: "r"(saddr), "l"(gaddr))
#define CP_COMMIT()   asm volatile("cp.async.commit_group;" ::: "memory")
#define CP_WAIT(n)    asm volatile("cp.async.wait_group %0;" :: "n"(n) : "memory")

#define MMA_TF32(c, a, bf) \
    asm volatile("mma.sync.aligned.m16n8k8.row.col.f32.tf32.tf32.f32 " \
        "{%0,%1,%2,%3}, {%4,%5,%6,%7}, {%8,%9}, {%0,%1,%2,%3};" \
        : "+f"((c)[0]), "+f"((c)[1]), "+f"((c)[2]), "+f"((c)[3]) \
        : "r"((a)[0]), "r"((a)[1]), "r"((a)[2]), "r"((a)[3]), \
          "r"((bf)[0]), "r"((bf)[1]))

#define MMA_F16(c, a, bf) \
    asm volatile("mma.sync.aligned.m16n8k16.row.col.f32.f16.f16.f32 " \
        "{%0,%1,%2,%3}, {%4,%5,%6,%7}, {%8,%9}, {%0,%1,%2,%3};" \
        : "+f"((c)[0]), "+f"((c)[1]), "+f"((c)[2]), "+f"((c)[3]) \
        : "r"((a)[0]), "r"((a)[1]), "r"((a)[2]), "r"((a)[3]), \
          "r"((bf)[0]), "r"((bf)[1]))

// ---------------- wconv: pack W to half2 ----------------
__global__ void wconv_kernel(const float* __restrict__ W) {
    int idx4 = blockIdx.x * 256 + threadIdx.x;     // float4 id, 32768 total
    float4 v = *(const float4*)(W + (size_t)idx4 * 4);
    uint2 u;
    u.x = pack_h2(v.x, v.y);
    u.y = pack_h2(v.z, v.w);
    *(uint2*)(g_Wh2 + (size_t)idx4 * 2) = u;
}

// ---------------- predsum ----------------
__global__ void predsum_kernel(const float* __restrict__ preds) {
    int b = blockIdx.x;
    const float* pr = preds + (size_t)b * HW;
    int t = threadIdx.x;
    float s = 0.f;
    for (int i = t; i < HW; i += 256) s += pr[i];
    s = warp_sum(s);
    __shared__ float red[8];
    if ((t & 31) == 0) red[t >> 5] = s;
    __syncthreads();
    if (t == 0) {
        float tt = 0.f;
#pragma unroll
        for (int j = 0; j < 8; j++) tt += red[j];
        g_predsum[b] = tt;
    }
}

// ---------------- pooled: reduce 32 partials, then W @ g ----------------
__global__ void pooled_kernel(const float* __restrict__ W,
                              const float* __restrict__ bias) {
    __shared__ float gs[CIN];
    int b = blockIdx.x;
    int t = threadIdx.x;
    float s0 = 0.f, s1 = 0.f;
#pragma unroll
    for (int si = 0; si < NXT; si++) {
        s0 += g_part[si][b][t];
        s1 += g_part[si][b][t + 256];
    }
    gs[t] = s0;
    gs[t + 256] = s1;
    __syncthreads();
    const float* wr = W + (size_t)t * CIN;
    float s = 0.f;
#pragma unroll 8
    for (int c = 0; c < CIN; c++) s += wr[c] * gs[c];
    g_pooled[b * COUT + t] = (s + bias[t] * g_predsum[b]) * (1.0f / (float)HW);
}

// ---------------- memscan (unchanged) ----------------
__global__ void memscan_kernel(const int* __restrict__ epoch_p) {
    __shared__ float px[32 * 264];
    __shared__ float ms[32 * 264];
    __shared__ float rxs[32];
    __shared__ float m2s[32];
    __shared__ float sims[32];
    __shared__ int   s_ptr;

    int t = threadIdx.x, w = t >> 5, lane = t & 31;
    float threshold = ((float)(*epoch_p) / 10.0f - 2.0f) * 0.4f / 13.0f + 0.3f;

    for (int i = t; i < 2048; i += 1024) {
        int row = i >> 6, c4 = (i & 63) * 4;
        *(float4*)&px[row * 264 + c4] = *(const float4*)&g_pooled[row * 256 + c4];
    }
    if (t == 0) s_ptr = 0;
    __syncthreads();

    {
        float s = 0.f;
#pragma unroll
        for (int j = 0; j < 8; j++) {
            float v = px[w * 264 + lane + 32 * j];
            s += v * v;
        }
        s = warp_sum(s);
        if (lane == 0) rxs[w] = rsqrtf(s);
    }
    __syncthreads();

    for (int i = 0; i < BATCH; i++) {
        int ptr = s_ptr;
        float d = 0.f;
        if (w < ptr) {
#pragma unroll
            for (int j = 0; j < 8; j++)
                d += ms[w * 264 + lane + 32 * j] * px[i * 264 + lane + 32 * j];
        }
        d = warp_sum(d);
        if (lane == 0) {
            if (w < ptr) {
                float m2 = m2s[w];
                float rm = (m2 == 0.f) ? 1.0f : rsqrtf(m2);
                sims[w] = d * rm * rxs[i];
            } else {
                sims[w] = -INFINITY;
            }
        }
        __syncthreads();
        if (w == 0) {
            float bv = sims[lane];
            int   bi = lane;
#pragma unroll
            for (int o = 16; o; o >>= 1) {
                float ov = __shfl_xor_sync(0xffffffffu, bv, o);
                int   oi = __shfl_xor_sync(0xffffffffu, bi, o);
                if (ov > bv || (ov == bv && oi < bi)) { bv = ov; bi = oi; }
            }
            int ema = (ptr > 0) && (bv >= threshold);
            int idx = ema ? bi : ptr;
            float ns2 = 0.f;
#pragma unroll
            for (int j = 0; j < 8; j++) {
                int c = lane + 32 * j;
                float xv = px[i * 264 + c];
                float nv = ema ? (ms[idx * 264 + c] * 0.9f + 0.1f * xv) : xv;
                ms[idx * 264 + c] = nv;
                ns2 += nv * nv;
            }
            ns2 = warp_sum(ns2);
            if (lane == 0) {
                m2s[idx] = ns2;
                if (!ema) s_ptr = ptr + 1;
            }
        }
        __syncthreads();
    }

    int ptr = s_ptr;
    for (int i = t; i < ptr * 256; i += 1024)
        g_mem[i] = ms[(i >> 8) * 264 + (i & 255)];
    if (t == 0) g_ptr = ptr;
}

// ---------------- proj GEMM v4: BM=256, A streamed from L2 ---------------
__global__ __launch_bounds__(NTHREADS, 1)
void proj_mma(const float* __restrict__ feats,
              const float* __restrict__ preds,
              const float* __restrict__ bias,
              float* __restrict__ out) {
    extern __shared__ char smem[];
    float* Bs   = (float*)smem;                    // 8 stages [16][132] fp32
    float* pbuf = (float*)(smem + PBUF_OFF);
    float* gacc = (float*)(smem + GACC_OFF);

    int t = threadIdx.x, wid = t >> 5, lane = t & 31;
    int g = lane >> 2, tg = lane & 3;
    int b  = blockIdx.y;
    int n0 = blockIdx.x * BN;
    int warp_m = (wid >> 1) * 64;       // 0,64,128,192
    int warp_n = (wid & 1) * 64;        // 0,64

    const float* fb = feats + (size_t)b * CIN * HW + n0;
    uint32_t sB = smem_u32(Bs);

    if (t < 128) pbuf[t] = preds[(size_t)b * HW + n0 + t];

    // pipeline fill: stages 0..NSTB-2
#pragma unroll
    for (int s = 0; s < NSTB - 1; s++) {
#pragma unroll
        for (int i = 0; i < 2; i++) {
            int c = t + i * NTHREADS;   // 16B chunk id, 512 total
            int row = c >> 5, col16 = c & 31;
            CP_ASYNC16(sB + s * B_STAGE_BYTES + row * (B_STRIDE * 4) + col16 * 16,
                       fb + (size_t)(s * BK + row) * HW + col16 * 4);
        }
        CP_COMMIT();
    }

    float acc[4][8][4];
#pragma unroll
    for (int mt = 0; mt < 4; mt++)
#pragma unroll
        for (int nt = 0; nt < 8; nt++)
#pragma unroll
            for (int q = 0; q < 4; q++) acc[mt][nt][q] = 0.f;

    for (int kt = 0; kt < NKT; kt++) {
        CP_WAIT(6);
        __syncthreads();
        if (kt + NSTB - 1 < NKT) {
            int s = (kt + NSTB - 1) & (NSTB - 1);
#pragma unroll
            for (int i = 0; i < 2; i++) {
                int c = t + i * NTHREADS;
                int row = c >> 5, col16 = c & 31;
                CP_ASYNC16(sB + s * B_STAGE_BYTES + row * (B_STRIDE * 4) + col16 * 16,
                           fb + (size_t)((kt + NSTB - 1) * BK + row) * HW + col16 * 4);
            }
        }
        CP_COMMIT();

        const float* BsS = Bs + (kt & (NSTB - 1)) * (BK * B_STRIDE);

        // fused g partial: g[b, kt*16+kk] += sum_n feats*preds
        {
            int kk = t >> 4, seg = t & 15;
            float s = 0.f;
#pragma unroll
            for (int j = 0; j < 8; j++)
                s += BsS[kk * B_STRIDE + seg + 16 * j] * pbuf[seg + 16 * j];
#pragma unroll
            for (int o = 8; o; o >>= 1) s += __shfl_down_sync(0xffffffffu, s, o, 16);
            if (seg == 0) gacc[kt * 16 + kk] = s;
        }

        // B fragments (shared across mt)
        uint32_t bf[8][2];
        {
            const float* bk0 = BsS + (2 * tg) * B_STRIDE;       // k = 2tg
#pragma unroll
            for (int nt = 0; nt < 8; nt++) {
                int n = warp_n + nt * 8 + g;
                bf[nt][0] = pack_h2(bk0[n],                 bk0[B_STRIDE + n]);
                bf[nt][1] = pack_h2(bk0[8 * B_STRIDE + n],  bk0[9 * B_STRIDE + n]);
            }
        }
        // A fragments streamed from L2-resident g_Wh2
#pragma unroll
        for (int mt = 0; mt < 4; mt++) {
            const uint32_t* ap = g_Wh2 + (size_t)(warp_m + mt * 16 + g) * (CIN / 2)
                                 + kt * 8 + tg;
            uint32_t af[4];
            af[0] = __ldg(ap);
            af[1] = __ldg(ap + 8 * (CIN / 2));
            af[2] = __ldg(ap + 4);
            af[3] = __ldg(ap + 8 * (CIN / 2) + 4);
#pragma unroll
            for (int nt = 0; nt < 8; nt++)
                MMA_F16(acc[mt][nt], af, bf[nt]);
        }
    }
    __syncthreads();

    g_part[blockIdx.x][b][t]       = gacc[t];
    g_part[blockIdx.x][b][t + 256] = gacc[t + 256];

#pragma unroll
    for (int mt = 0; mt < 4; mt++) {
        int m = warp_m + mt * 16 + g;
        float bv0 = bias[m], bv1 = bias[m + 8];
        float* rowp = out + ((size_t)b * (2 * COUT) + m) * HW + n0 + warp_n + 2 * tg;
#pragma unroll
        for (int nt = 0; nt < 8; nt++) {
            *(float2*)(rowp + nt * 8)          = make_float2(acc[mt][nt][0] + bv0, acc[mt][nt][1] + bv0);
            *(float2*)(rowp + nt * 8 + 8 * HW) = make_float2(acc[mt][nt][2] + bv1, acc[mt][nt][3] + bv1);
        }
    }
}

// ---------------- attention v3 (unchanged) ----------------
__global__ __launch_bounds__(256, 2)
void attn_mma(float* __restrict__ out) {
    extern __shared__ char smc[];
    float* memS = (float*)(smc + AT_MEMS_OFF);
    float* lsm  = (float*)(smc + AT_LSM_OFF);
    float* stg  = (float*)(smc + AT_STG_OFF);

    int t = threadIdx.x, wid = t >> 5, lane = t & 31;
    int g = lane >> 2, tg = lane & 3;
    int b = blockIdx.y, l0 = blockIdx.x * 128;
    int ptr = g_ptr;

    for (int idx = t; idx < 32 * 256; idx += 256) {
        int p = idx >> 8, c = idx & 255;
        memS[p * MS_STRIDE + c] = (p < ptr) ? g_mem[idx] : 0.f;
    }

    const float* proj = out + (size_t)b * (2 * COUT) * HW;
    float* aug = out + (size_t)b * (2 * COUT) * HW + (size_t)COUT * HW + l0;
    uint32_t sStg = smem_u32(stg);

#define AT_LOAD(sidx, ktile) do {                                              \
    _Pragma("unroll")                                                          \
    for (int i = 0; i < 2; i++) {                                              \
        int c = t + i * 256;                                                   \
        int r = c >> 5, c16 = c & 31;                                          \
        CP_ASYNC16(sStg + (sidx) * AT_STAGE_BYTES + r * (LS_STRIDE * 4) + c16 * 16, \
                   proj + (size_t)((ktile) * 16 + r) * HW + l0 + c16 * 4);     \
    } } while (0)

    AT_LOAD(0, 0); CP_COMMIT();
    AT_LOAD(1, 1); CP_COMMIT();
    AT_LOAD(2, 2); CP_COMMIT();

    float accl[2][2][4];
#pragma unroll
    for (int mt = 0; mt < 2; mt++)
#pragma unroll
        for (int nt = 0; nt < 2; nt++)
#pragma unroll
            for (int q = 0; q < 4; q++) accl[mt][nt][q] = 0.f;
    int n0w = wid * 16;

    for (int kt = 0; kt < 16; kt++) {
        CP_WAIT(2);
        __syncthreads();
        if (kt + 3 < 16) AT_LOAD((kt + 3) & 3, kt + 3);
        CP_COMMIT();

        const float* BsS = stg + (kt & 3) * (16 * LS_STRIDE);
#pragma unroll
        for (int kk = 0; kk < 2; kk++) {
            int kc = kt * 16 + kk * 8;
            uint32_t af[2][4];
#pragma unroll
            for (int mt = 0; mt < 2; mt++) {
                const float* ap = memS + (mt * 16 + g) * MS_STRIDE + kc + tg;
                af[mt][0] = f2tf32(ap[0]);
                af[mt][1] = f2tf32(ap[8 * MS_STRIDE]);
                af[mt][2] = f2tf32(ap[4]);
                af[mt][3] = f2tf32(ap[8 * MS_STRIDE + 4]);
            }
            uint32_t bf[2][2];
#pragma unroll
            for (int nt = 0; nt < 2; nt++) {
                const float* bp = BsS + (kk * 8 + tg) * LS_STRIDE + n0w + nt * 8 + g;
                bf[nt][0] = f2tf32(bp[0]);
                bf[nt][1] = f2tf32(bp[4 * LS_STRIDE]);
            }
#pragma unroll
            for (int mt = 0; mt < 2; mt++)
#pragma unroll
                for (int nt = 0; nt < 2; nt++)
                    MMA_TF32(accl[mt][nt], af[mt], bf[nt]);
        }
    }
    __syncthreads();
#pragma unroll
    for (int mt = 0; mt < 2; mt++)
#pragma unroll
        for (int nt = 0; nt < 2; nt++) {
            int p = mt * 16 + g;
            int l = n0w + nt * 8 + 2 * tg;
            *(float2*)&lsm[p * LS_STRIDE + l]       = make_float2(accl[mt][nt][0], accl[mt][nt][1]);
            *(float2*)&lsm[(p + 8) * LS_STRIDE + l] = make_float2(accl[mt][nt][2], accl[mt][nt][3]);
        }
    __syncthreads();

    if (t < 128) {
        float mx = -INFINITY;
        for (int p = 0; p < ptr; p++) mx = fmaxf(mx, lsm[p * LS_STRIDE + t]);
        float ss = 0.f;
        for (int p = 0; p < ptr; p++) {
            float e = expf(lsm[p * LS_STRIDE + t] - mx);
            lsm[p * LS_STRIDE + t] = e;
            ss += e;
        }
        float inv = 1.0f / ss;
        for (int p = 0; p < ptr; p++) lsm[p * LS_STRIDE + t] *= inv;
        for (int p = ptr; p < 32; p++) lsm[p * LS_STRIDE + t] = 0.f;
    }
    __syncthreads();

    int m0w = wid * 32;
#pragma unroll
    for (int nh = 0; nh < 2; nh++) {
        float acca[2][8][4];
#pragma unroll
        for (int mt = 0; mt < 2; mt++)
#pragma unroll
            for (int nt = 0; nt < 8; nt++)
#pragma unroll
                for (int q = 0; q < 4; q++) acca[mt][nt][q] = 0.f;
#pragma unroll
        for (int ks = 0; ks < 4; ks++) {
            uint32_t af[2][4];
#pragma unroll
            for (int mt = 0; mt < 2; mt++) {
                const float* ap = memS + (ks * 8 + tg) * MS_STRIDE + m0w + mt * 16 + g;
                af[mt][0] = f2tf32(ap[0]);
                af[mt][1] = f2tf32(ap[8]);
                af[mt][2] = f2tf32(ap[4 * MS_STRIDE]);
                af[mt][3] = f2tf32(ap[4 * MS_STRIDE + 8]);
            }
            uint32_t bf[8][2];
#pragma unroll
            for (int nt = 0; nt < 8; nt++) {
                const float* bp = lsm + (ks * 8 + tg) * LS_STRIDE + nh * 64 + nt * 8 + g;
                bf[nt][0] = f2tf32(bp[0]);
                bf[nt][1] = f2tf32(bp[4 * LS_STRIDE]);
            }
#pragma unroll
            for (int mt = 0; mt < 2; mt++)
#pragma unroll
                for (int nt = 0; nt < 8; nt++)
                    MMA_TF32(acca[mt][nt], af[mt], bf[nt]);
        }
#pragma unroll
        for (int mt = 0; mt < 2; mt++) {
            int c = m0w + mt * 16 + g;
            float* r0 = aug + (size_t)c * HW + nh * 64 + 2 * tg;
            float* r1 = r0 + (size_t)8 * HW;
#pragma unroll
            for (int nt = 0; nt < 8; nt++) {
                *(float2*)(r0 + nt * 8) = make_float2(acca[mt][nt][0], acca[mt][nt][1]);
                *(float2*)(r1 + nt * 8) = make_float2(acca[mt][nt][2], acca[mt][nt][3]);
            }
        }
    }
#undef AT_LOAD
}

// ---------------- launch --------------------------------------------------
extern "C" void kernel_launch(void* const* d_in, const int* in_sizes, int n_in,
                              void* d_out, int out_size) {
    const float* feats = (const float*)d_in[0];
    const float* preds = (const float*)d_in[1];
    const float* W     = (const float*)d_in[2];
    const float* bias  = (const float*)d_in[3];
    const int*   epoch = (const int*)d_in[4];
    float* out = (float*)d_out;

    cudaFuncSetAttribute(proj_mma, cudaFuncAttributeMaxDynamicSharedMemorySize, SMEM_TOTAL);
    cudaFuncSetAttribute(attn_mma, cudaFuncAttributeMaxDynamicSharedMemorySize, AT_SMEM_TOTAL);

    wconv_kernel<<<128, 256>>>(W);
    predsum_kernel<<<BATCH, 256>>>(preds);
    proj_mma<<<dim3(NXT, BATCH), NTHREADS, SMEM_TOTAL>>>(feats, preds, bias, out);
    pooled_kernel<<<BATCH, 256>>>(W, bias);
    memscan_kernel<<<1, 1024>>>(epoch);
    attn_mma<<<dim3(HW / 128, BATCH), 256, AT_SMEM_TOTAL>>>(out);
}

// round 11
// speedup vs baseline: 1.2908x; 1.2908x over previous
#include <cuda_runtime.h>
#include <cuda_fp16.h>
#include <math.h>
#include <stdint.h>

#define HW    4096
#define CIN   512
#define COUT  256
#define BATCH 32

// ---- proj GEMM tiling (R9 known-good: fp16 MMA, BM=128, 512 thr) ----
#define BM 128
#define BN 256
#define BK 16
#define NKT (CIN / BK)
#define NSTB 4
#define NTHREADS 512
#define NXT (HW / BN)           // 16 n-tiles
#define A_STRIDE_U32 260
#define B_STRIDE 268
#define A_BYTES (BM * A_STRIDE_U32 * 4)       // 133120
#define B_STAGE_BYTES (BK * B_STRIDE * 4)     // 17152
#define PBUF_OFF (A_BYTES + NSTB * B_STAGE_BYTES)   // 201728
#define GACC_OFF (PBUF_OFF + 256 * 4)               // 202752
#define SMEM_TOTAL (GACC_OFF + 512 * 4)             // 204800

// ---- attn smem layout (unchanged) ----
#define MS_STRIDE 260
#define LS_STRIDE 136
#define AT_MEMS_OFF 0
#define AT_LSM_OFF  (32 * MS_STRIDE * 4)
#define AT_STG_OFF  (AT_LSM_OFF + 32 * LS_STRIDE * 4)
#define AT_STAGE_BYTES (16 * LS_STRIDE * 4)
#define AT_SMEM_TOTAL (AT_STG_OFF + 4 * AT_STAGE_BYTES) // 85504

// ---------------- device scratch ----------------
// g_part transposed: [b][c][n-tile] so pooled reduces CONTIGUOUS 16 floats
__device__ float g_part[BATCH][CIN][NXT];
__device__ float g_predsum[BATCH];
__device__ float g_pooled[BATCH * COUT];
__device__ float g_mem[BATCH * COUT];
__device__ int   g_ptr;

__device__ __forceinline__ float warp_sum(float v) {
#pragma unroll
    for (int o = 16; o; o >>= 1) v += __shfl_down_sync(0xffffffffu, v, o);
    return v;
}
__device__ __forceinline__ uint32_t smem_u32(const void* p) {
    uint32_t a;
    asm("{ .reg .u64 t; cvta.to.shared.u64 t, %1; cvt.u32.u64 %0, t; }" : "=r"(a) : "l"(p));
    return a;
}
__device__ __forceinline__ uint32_t f2tf32(float f) {
    uint32_t r;
    asm("cvt.rna.tf32.f32 %0, %1;" : "=r"(r) : "f"(f));
    return r;
}
__device__ __forceinline__ uint32_t pack_h2(float lo, float hi) {
    __half2 h = __floats2half2_rn(lo, hi);
    return *(uint32_t*)&h;
}
#define CP_ASYNC16(saddr, gaddr) \
    asm volatile("cp.async.cg.shared.global [%0], [%1], 16;" :: "r"(saddr), "l"(gaddr))
#define CP_COMMIT()   asm volatile("cp.async.commit_group;" ::: "memory")
#define CP_WAIT(n)    asm volatile("cp.async.wait_group %0;" :: "n"(n) : "memory")

#define MMA_TF32(c, a, bf) \
    asm volatile("mma.sync.aligned.m16n8k8.row.col.f32.tf32.tf32.f32 " \
        "{%0,%1,%2,%3}, {%4,%5,%6,%7}, {%8,%9}, {%0,%1,%2,%3};" \
        : "+f"((c)[0]), "+f"((c)[1]), "+f"((c)[2]), "+f"((c)[3]) \
        : "r"((a)[0]), "r"((a)[1]), "r"((a)[2]), "r"((a)[3]), \
          "r"((bf)[0]), "r"((bf)[1]))

#define MMA_F16(c, a, bf) \
    asm volatile("mma.sync.aligned.m16n8k16.row.col.f32.f16.f16.f32 " \
        "{%0,%1,%2,%3}, {%4,%5,%6,%7}, {%8,%9}, {%0,%1,%2,%3};" \
        : "+f"((c)[0]), "+f"((c)[1]), "+f"((c)[2]), "+f"((c)[3]) \
        : "r"((a)[0]), "r"((a)[1]), "r"((a)[2]), "r"((a)[3]), \
          "r"((bf)[0]), "r"((bf)[1]))

// ---------------- predsum ----------------
__global__ void predsum_kernel(const float* __restrict__ preds) {
    int b = blockIdx.x;
    const float* pr = preds + (size_t)b * HW;
    int t = threadIdx.x;
    float s = 0.f;
    for (int i = t; i < HW; i += 256) s += pr[i];
    s = warp_sum(s);
    __shared__ float red[8];
    if ((t & 31) == 0) red[t >> 5] = s;
    __syncthreads();
    if (t == 0) {
        float tt = 0.f;
#pragma unroll
        for (int j = 0; j < 8; j++) tt += red[j];
        g_predsum[b] = tt;
    }
}

// ---------------- pooled v2: coalesced reduce + 4-thread dot ----------------
__global__ void pooled_kernel(const float* __restrict__ W,
                              const float* __restrict__ bias) {
    __shared__ float gs[CIN];
    int b = blockIdx.x;
    int t = threadIdx.x;       // 1024 threads

    // Phase A: each of 512 threads reduces one channel's 16 contiguous partials
    if (t < CIN) {
        const float* pp = &g_part[b][t][0];
        float4 v0 = *(const float4*)(pp + 0);
        float4 v1 = *(const float4*)(pp + 4);
        float4 v2 = *(const float4*)(pp + 8);
        float4 v3 = *(const float4*)(pp + 12);
        gs[t] = ((v0.x + v0.y) + (v0.z + v0.w)) + ((v1.x + v1.y) + (v1.z + v1.w))
              + ((v2.x + v2.y) + (v2.z + v2.w)) + ((v3.x + v3.y) + (v3.z + v3.w));
    }
    __syncthreads();

    // Phase B: 4 threads per output channel, 128 MACs each
    int o = t >> 2, q = t & 3;
    const float* wr = W + (size_t)o * CIN + q;
    float s = 0.f;
#pragma unroll 16
    for (int j = 0; j < 128; j++) s += wr[4 * j] * gs[q + 4 * j];
#pragma unroll
    for (int sh = 2; sh; sh >>= 1) s += __shfl_down_sync(0xffffffffu, s, sh, 4);
    if (q == 0)
        g_pooled[b * COUT + o] = (s + bias[o] * g_predsum[b]) * (1.0f / (float)HW);
}

// ---------------- memscan (unchanged) ----------------
__global__ void memscan_kernel(const int* __restrict__ epoch_p) {
    __shared__ float px[32 * 264];
    __shared__ float ms[32 * 264];
    __shared__ float rxs[32];
    __shared__ float m2s[32];
    __shared__ float sims[32];
    __shared__ int   s_ptr;

    int t = threadIdx.x, w = t >> 5, lane = t & 31;
    float threshold = ((float)(*epoch_p) / 10.0f - 2.0f) * 0.4f / 13.0f + 0.3f;

    for (int i = t; i < 2048; i += 1024) {
        int row = i >> 6, c4 = (i & 63) * 4;
        *(float4*)&px[row * 264 + c4] = *(const float4*)&g_pooled[row * 256 + c4];
    }
    if (t == 0) s_ptr = 0;
    __syncthreads();

    {
        float s = 0.f;
#pragma unroll
        for (int j = 0; j < 8; j++) {
            float v = px[w * 264 + lane + 32 * j];
            s += v * v;
        }
        s = warp_sum(s);
        if (lane == 0) rxs[w] = rsqrtf(s);
    }
    __syncthreads();

    for (int i = 0; i < BATCH; i++) {
        int ptr = s_ptr;
        float d = 0.f;
        if (w < ptr) {
#pragma unroll
            for (int j = 0; j < 8; j++)
                d += ms[w * 264 + lane + 32 * j] * px[i * 264 + lane + 32 * j];
        }
        d = warp_sum(d);
        if (lane == 0) {
            if (w < ptr) {
                float m2 = m2s[w];
                float rm = (m2 == 0.f) ? 1.0f : rsqrtf(m2);
                sims[w] = d * rm * rxs[i];
            } else {
                sims[w] = -INFINITY;
            }
        }
        __syncthreads();
        if (w == 0) {
            float bv = sims[lane];
            int   bi = lane;
#pragma unroll
            for (int o = 16; o; o >>= 1) {
                float ov = __shfl_xor_sync(0xffffffffu, bv, o);
                int   oi = __shfl_xor_sync(0xffffffffu, bi, o);
                if (ov > bv || (ov == bv && oi < bi)) { bv = ov; bi = oi; }
            }
            int ema = (ptr > 0) && (bv >= threshold);
            int idx = ema ? bi : ptr;
            float ns2 = 0.f;
#pragma unroll
            for (int j = 0; j < 8; j++) {
                int c = lane + 32 * j;
                float xv = px[i * 264 + c];
                float nv = ema ? (ms[idx * 264 + c] * 0.9f + 0.1f * xv) : xv;
                ms[idx * 264 + c] = nv;
                ns2 += nv * nv;
            }
            ns2 = warp_sum(ns2);
            if (lane == 0) {
                m2s[idx] = ns2;
                if (!ema) s_ptr = ptr + 1;
            }
        }
        __syncthreads();
    }

    int ptr = s_ptr;
    for (int i = t; i < ptr * 256; i += 1024)
        g_mem[i] = ms[(i >> 8) * 264 + (i & 255)];
    if (t == 0) g_ptr = ptr;
}

// ---------------- proj GEMM (R9 known-good) + transposed g writes --------
__global__ __launch_bounds__(NTHREADS, 1)
void proj_mma(const float* __restrict__ feats,
              const float* __restrict__ preds,
              const float* __restrict__ W,
              const float* __restrict__ bias,
              float* __restrict__ out) {
    extern __shared__ char smem[];
    uint32_t* Au  = (uint32_t*)smem;               // A: [128][260] half2
    float* Bs     = (float*)(smem + A_BYTES);      // 4 stages [16][268] fp32
    float* pbuf   = (float*)(smem + PBUF_OFF);
    float* gacc   = (float*)(smem + GACC_OFF);

    int t = threadIdx.x, wid = t >> 5, lane = t & 31;
    int g = lane >> 2, tg = lane & 3;
    int b  = blockIdx.z;
    int m0 = blockIdx.y * BM;
    int n0 = blockIdx.x * BN;
    int warp_m = (wid >> 2) * 32;
    int warp_n = (wid & 3) * 64;
    bool do_g = (blockIdx.y == 0);

    const float* fb = feats + (size_t)b * CIN * HW + n0;
    uint32_t sB = smem_u32(Bs);

    if (do_g && t < 256) pbuf[t] = preds[(size_t)b * HW + n0 + t];

    // stage A slice (128 x 512) as packed half2
#pragma unroll
    for (int i = 0; i < 32; i++) {
        int c = t + i * NTHREADS;
        int row = c >> 7, col4 = (c & 127) * 4;
        float4 v = *(const float4*)(W + (size_t)(m0 + row) * CIN + col4);
        uint2 u;
        u.x = pack_h2(v.x, v.y);
        u.y = pack_h2(v.z, v.w);
        *(uint2*)(Au + row * A_STRIDE_U32 + (c & 127) * 2) = u;
    }

#pragma unroll
    for (int s = 0; s < NSTB - 1; s++) {
#pragma unroll
        for (int i = 0; i < 2; i++) {
            int c = t + i * NTHREADS;
            int row = c >> 6, col16 = c & 63;
            CP_ASYNC16(sB + s * B_STAGE_BYTES + row * (B_STRIDE * 4) + col16 * 16,
                       fb + (size_t)(s * BK + row) * HW + col16 * 4);
        }
        CP_COMMIT();
    }

    float acc[2][8][4];
#pragma unroll
    for (int mt = 0; mt < 2; mt++)
#pragma unroll
        for (int nt = 0; nt < 8; nt++)
#pragma unroll
            for (int q = 0; q < 4; q++) acc[mt][nt][q] = 0.f;

    for (int kt = 0; kt < NKT; kt++) {
        CP_WAIT(2);
        __syncthreads();
        if (kt + NSTB - 1 < NKT) {
            int s = (kt + NSTB - 1) & (NSTB - 1);
#pragma unroll
            for (int i = 0; i < 2; i++) {
                int c = t + i * NTHREADS;
                int row = c >> 6, col16 = c & 63;
                CP_ASYNC16(sB + s * B_STAGE_BYTES + row * (B_STRIDE * 4) + col16 * 16,
                           fb + (size_t)((kt + NSTB - 1) * BK + row) * HW + col16 * 4);
            }
        }
        CP_COMMIT();

        const float* BsS = Bs + (kt & (NSTB - 1)) * (BK * B_STRIDE);

        if (do_g && t < 256) {
            int kk = t >> 4, seg = t & 15;
            float s = 0.f;
#pragma unroll
            for (int j = 0; j < 16; j++)
                s += BsS[kk * B_STRIDE + seg + 16 * j] * pbuf[seg + 16 * j];
#pragma unroll
            for (int o = 8; o; o >>= 1) s += __shfl_down_sync(0xffffffffu, s, o, 16);
            if (seg == 0) gacc[kt * 16 + kk] = s;
        }

        uint32_t af[2][4];
#pragma unroll
        for (int mt = 0; mt < 2; mt++) {
            const uint32_t* ap = Au + (size_t)(warp_m + mt * 16 + g) * A_STRIDE_U32
                                 + kt * 8 + tg;
            af[mt][0] = ap[0];
            af[mt][1] = ap[8 * A_STRIDE_U32];
            af[mt][2] = ap[4];
            af[mt][3] = ap[8 * A_STRIDE_U32 + 4];
        }
        uint32_t bf[8][2];
        {
            const float* bk0 = BsS + (2 * tg) * B_STRIDE;
#pragma unroll
            for (int nt = 0; nt < 8; nt++) {
                int n = warp_n + nt * 8 + g;
                bf[nt][0] = pack_h2(bk0[n],                 bk0[B_STRIDE + n]);
                bf[nt][1] = pack_h2(bk0[8 * B_STRIDE + n],  bk0[9 * B_STRIDE + n]);
            }
        }
#pragma unroll
        for (int mt = 0; mt < 2; mt++)
#pragma unroll
            for (int nt = 0; nt < 8; nt++)
                MMA_F16(acc[mt][nt], af[mt], bf[nt]);
    }
    __syncthreads();

    // transposed partial write: g_part[b][c][n-tile]
    if (do_g && t < 256) {
        g_part[b][t][blockIdx.x]       = gacc[t];
        g_part[b][t + 256][blockIdx.x] = gacc[t + 256];
    }

#pragma unroll
    for (int mt = 0; mt < 2; mt++) {
        int m = m0 + warp_m + mt * 16 + g;
        float bv0 = bias[m], bv1 = bias[m + 8];
        float* rowp = out + ((size_t)b * (2 * COUT) + m) * HW + n0 + warp_n + 2 * tg;
#pragma unroll
        for (int nt = 0; nt < 8; nt++) {
            *(float2*)(rowp + nt * 8)          = make_float2(acc[mt][nt][0] + bv0, acc[mt][nt][1] + bv0);
            *(float2*)(rowp + nt * 8 + 8 * HW) = make_float2(acc[mt][nt][2] + bv1, acc[mt][nt][3] + bv1);
        }
    }
}

// ---------------- attention v3 (unchanged) ----------------
__global__ __launch_bounds__(256, 2)
void attn_mma(float* __restrict__ out) {
    extern __shared__ char smc[];
    float* memS = (float*)(smc + AT_MEMS_OFF);
    float* lsm  = (float*)(smc + AT_LSM_OFF);
    float* stg  = (float*)(smc + AT_STG_OFF);

    int t = threadIdx.x, wid = t >> 5, lane = t & 31;
    int g = lane >> 2, tg = lane & 3;
    int b = blockIdx.y, l0 = blockIdx.x * 128;
    int ptr = g_ptr;

    for (int idx = t; idx < 32 * 256; idx += 256) {
        int p = idx >> 8, c = idx & 255;
        memS[p * MS_STRIDE + c] = (p < ptr) ? g_mem[idx] : 0.f;
    }

    const float* proj = out + (size_t)b * (2 * COUT) * HW;
    float* aug = out + (size_t)b * (2 * COUT) * HW + (size_t)COUT * HW + l0;
    uint32_t sStg = smem_u32(stg);

#define AT_LOAD(sidx, ktile) do {                                              \
    _Pragma("unroll")                                                          \
    for (int i = 0; i < 2; i++) {                                              \
        int c = t + i * 256;                                                   \
        int r = c >> 5, c16 = c & 31;                                          \
        CP_ASYNC16(sStg + (sidx) * AT_STAGE_BYTES + r * (LS_STRIDE * 4) + c16 * 16, \
                   proj + (size_t)((ktile) * 16 + r) * HW + l0 + c16 * 4);     \
    } } while (0)

    AT_LOAD(0, 0); CP_COMMIT();
    AT_LOAD(1, 1); CP_COMMIT();
    AT_LOAD(2, 2); CP_COMMIT();

    float accl[2][2][4];
#pragma unroll
    for (int mt = 0; mt < 2; mt++)
#pragma unroll
        for (int nt = 0; nt < 2; nt++)
#pragma unroll
            for (int q = 0; q < 4; q++) accl[mt][nt][q] = 0.f;
    int n0w = wid * 16;

    for (int kt = 0; kt < 16; kt++) {
        CP_WAIT(2);
        __syncthreads();
        if (kt + 3 < 16) AT_LOAD((kt + 3) & 3, kt + 3);
        CP_COMMIT();

        const float* BsS = stg + (kt & 3) * (16 * LS_STRIDE);
#pragma unroll
        for (int kk = 0; kk < 2; kk++) {
            int kc = kt * 16 + kk * 8;
            uint32_t af[2][4];
#pragma unroll
            for (int mt = 0; mt < 2; mt++) {
                const float* ap = memS + (mt * 16 + g) * MS_STRIDE + kc + tg;
                af[mt][0] = f2tf32(ap[0]);
                af[mt][1] = f2tf32(ap[8 * MS_STRIDE]);
                af[mt][2] = f2tf32(ap[4]);
                af[mt][3] = f2tf32(ap[8 * MS_STRIDE + 4]);
            }
            uint32_t bf[2][2];
#pragma unroll
            for (int nt = 0; nt < 2; nt++) {
                const float* bp = BsS + (kk * 8 + tg) * LS_STRIDE + n0w + nt * 8 + g;
                bf[nt][0] = f2tf32(bp[0]);
                bf[nt][1] = f2tf32(bp[4 * LS_STRIDE]);
            }
#pragma unroll
            for (int mt = 0; mt < 2; mt++)
#pragma unroll
                for (int nt = 0; nt < 2; nt++)
                    MMA_TF32(accl[mt][nt], af[mt], bf[nt]);
        }
    }
    __syncthreads();
#pragma unroll
    for (int mt = 0; mt < 2; mt++)
#pragma unroll
        for (int nt = 0; nt < 2; nt++) {
            int p = mt * 16 + g;
            int l = n0w + nt * 8 + 2 * tg;
            *(float2*)&lsm[p * LS_STRIDE + l]       = make_float2(accl[mt][nt][0], accl[mt][nt][1]);
            *(float2*)&lsm[(p + 8) * LS_STRIDE + l] = make_float2(accl[mt][nt][2], accl[mt][nt][3]);
        }
    __syncthreads();

    if (t < 128) {
        float mx = -INFINITY;
        for (int p = 0; p < ptr; p++) mx = fmaxf(mx, lsm[p * LS_STRIDE + t]);
        float ss = 0.f;
        for (int p = 0; p < ptr; p++) {
            float e = expf(lsm[p * LS_STRIDE + t] - mx);
            lsm[p * LS_STRIDE + t] = e;
            ss += e;
        }
        float inv = 1.0f / ss;
        for (int p = 0; p < ptr; p++) lsm[p * LS_STRIDE + t] *= inv;
        for (int p = ptr; p < 32; p++) lsm[p * LS_STRIDE + t] = 0.f;
    }
    __syncthreads();

    int m0w = wid * 32;
#pragma unroll
    for (int nh = 0; nh < 2; nh++) {
        float acca[2][8][4];
#pragma unroll
        for (int mt = 0; mt < 2; mt++)
#pragma unroll
            for (int nt = 0; nt < 8; nt++)
#pragma unroll
                for (int q = 0; q < 4; q++) acca[mt][nt][q] = 0.f;
#pragma unroll
        for (int ks = 0; ks < 4; ks++) {
            uint32_t af[2][4];
#pragma unroll
            for (int mt = 0; mt < 2; mt++) {
                const float* ap = memS + (ks * 8 + tg) * MS_STRIDE + m0w + mt * 16 + g;
                af[mt][0] = f2tf32(ap[0]);
                af[mt][1] = f2tf32(ap[8]);
                af[mt][2] = f2tf32(ap[4 * MS_STRIDE]);
                af[mt][3] = f2tf32(ap[4 * MS_STRIDE + 8]);
            }
            uint32_t bf[8][2];
#pragma unroll
            for (int nt = 0; nt < 8; nt++) {
                const float* bp = lsm + (ks * 8 + tg) * LS_STRIDE + nh * 64 + nt * 8 + g;
                bf[nt][0] = f2tf32(bp[0]);
                bf[nt][1] = f2tf32(bp[4 * LS_STRIDE]);
            }
#pragma unroll
            for (int mt = 0; mt < 2; mt++)
#pragma unroll
                for (int nt = 0; nt < 8; nt++)
                    MMA_TF32(acca[mt][nt], af[mt], bf[nt]);
        }
#pragma unroll
        for (int mt = 0; mt < 2; mt++) {
            int c = m0w + mt * 16 + g;
            float* r0 = aug + (size_t)c * HW + nh * 64 + 2 * tg;
            float* r1 = r0 + (size_t)8 * HW;
#pragma unroll
            for (int nt = 0; nt < 8; nt++) {
                *(float2*)(r0 + nt * 8) = make_float2(acca[mt][nt][0], acca[mt][nt][1]);
                *(float2*)(r1 + nt * 8) = make_float2(acca[mt][nt][2], acca[mt][nt][3]);
            }
        }
    }
#undef AT_LOAD
}

// ---------------- launch --------------------------------------------------
extern "C" void kernel_launch(void* const* d_in, const int* in_sizes, int n_in,
                              void* d_out, int out_size) {
    const float* feats = (const float*)d_in[0];
    const float* preds = (const float*)d_in[1];
    const float* W     = (const float*)d_in[2];
    const float* bias  = (const float*)d_in[3];
    const int*   epoch = (const int*)d_in[4];
    float* out = (float*)d_out;

    cudaFuncSetAttribute(proj_mma, cudaFuncAttributeMaxDynamicSharedMemorySize, SMEM_TOTAL);
    cudaFuncSetAttribute(attn_mma, cudaFuncAttributeMaxDynamicSharedMemorySize, AT_SMEM_TOTAL);

    predsum_kernel<<<BATCH, 256>>>(preds);
    proj_mma<<<dim3(NXT, COUT / BM, BATCH), NTHREADS, SMEM_TOTAL>>>(feats, preds, W, bias, out);
    pooled_kernel<<<BATCH, 1024>>>(W, bias);
    memscan_kernel<<<1, 1024>>>(epoch);
    attn_mma<<<dim3(HW / 128, BATCH), 256, AT_SMEM_TOTAL>>>(out);
}

// round 12
// speedup vs baseline: 1.2980x; 1.0055x over previous
#include <cuda_runtime.h>
#include <cuda_fp16.h>
#include <math.h>
#include <stdint.h>

#define HW    4096
#define CIN   512
#define COUT  256
#define BATCH 32

// ---- proj GEMM tiling (R11 known-good) ----
#define BM 128
#define BN 256
#define BK 16
#define NKT (CIN / BK)
#define NSTB 4
#define NTHREADS 512
#define NXT (HW / BN)           // 16 n-tiles
#define A_STRIDE_U32 260
#define B_STRIDE 268
#define A_BYTES (BM * A_STRIDE_U32 * 4)
#define B_STAGE_BYTES (BK * B_STRIDE * 4)
#define PBUF_OFF (A_BYTES + NSTB * B_STAGE_BYTES)
#define GACC_OFF (PBUF_OFF + 256 * 4)
#define SMEM_TOTAL (GACC_OFF + 512 * 4)             // 204800

// ---- attn v4 smem layout: l-tile 256, lsm overlaid on stages ----
#define AT_L 256
#define MS_STRIDE 260
#define LS_STRIDE 264
#define AT_MEMS_OFF 0
#define AT_STG_OFF (32 * MS_STRIDE * 4)              // 33280
#define AT_STAGE_BYTES (16 * LS_STRIDE * 4)          // 16896
#define AT_SMEM_TOTAL (AT_STG_OFF + 4 * AT_STAGE_BYTES) // 100864 -> 2 CTAs/SM

// ---------------- device scratch ----------------
__device__ float g_part[BATCH][CIN][NXT];
__device__ float g_predsum[BATCH];
__device__ float g_pooled[BATCH * COUT];
__device__ float g_mem[BATCH * COUT];
__device__ int   g_ptr;

__device__ __forceinline__ float warp_sum(float v) {
#pragma unroll
    for (int o = 16; o; o >>= 1) v += __shfl_down_sync(0xffffffffu, v, o);
    return v;
}
__device__ __forceinline__ uint32_t smem_u32(const void* p) {
    uint32_t a;
    asm("{ .reg .u64 t; cvta.to.shared.u64 t, %1; cvt.u32.u64 %0, t; }" : "=r"(a) : "l"(p));
    return a;
}
__device__ __forceinline__ uint32_t f2tf32(float f) {
    uint32_t r;
    asm("cvt.rna.tf32.f32 %0, %1;" : "=r"(r) : "f"(f));
    return r;
}
__device__ __forceinline__ uint32_t pack_h2(float lo, float hi) {
    __half2 h = __floats2half2_rn(lo, hi);
    return *(uint32_t*)&h;
}
#define CP_ASYNC16(saddr, gaddr) \
    asm volatile("cp.async.cg.shared.global [%0], [%1], 16;" :: "r"(saddr), "l"(gaddr))
#define CP_COMMIT()   asm volatile("cp.async.commit_group;" ::: "memory")
#define CP_WAIT(n)    asm volatile("cp.async.wait_group %0;" :: "n"(n) : "memory")

#define MMA_TF32(c, a, bf) \
    asm volatile("mma.sync.aligned.m16n8k8.row.col.f32.tf32.tf32.f32 " \
        "{%0,%1,%2,%3}, {%4,%5,%6,%7}, {%8,%9}, {%0,%1,%2,%3};" \
        : "+f"((c)[0]), "+f"((c)[1]), "+f"((c)[2]), "+f"((c)[3]) \
        : "r"((a)[0]), "r"((a)[1]), "r"((a)[2]), "r"((a)[3]), \
          "r"((bf)[0]), "r"((bf)[1]))

#define MMA_F16(c, a, bf) \
    asm volatile("mma.sync.aligned.m16n8k16.row.col.f32.f16.f16.f32 " \
        "{%0,%1,%2,%3}, {%4,%5,%6,%7}, {%8,%9}, {%0,%1,%2,%3};" \
        : "+f"((c)[0]), "+f"((c)[1]), "+f"((c)[2]), "+f"((c)[3]) \
        : "r"((a)[0]), "r"((a)[1]), "r"((a)[2]), "r"((a)[3]), \
          "r"((bf)[0]), "r"((bf)[1]))

// ---------------- predsum ----------------
__global__ void predsum_kernel(const float* __restrict__ preds) {
    int b = blockIdx.x;
    const float* pr = preds + (size_t)b * HW;
    int t = threadIdx.x;
    float s = 0.f;
    for (int i = t; i < HW; i += 256) s += pr[i];
    s = warp_sum(s);
    __shared__ float red[8];
    if ((t & 31) == 0) red[t >> 5] = s;
    __syncthreads();
    if (t == 0) {
        float tt = 0.f;
#pragma unroll
        for (int j = 0; j < 8; j++) tt += red[j];
        g_predsum[b] = tt;
    }
}

// ---------------- pooled v2 (R11) ----------------
__global__ void pooled_kernel(const float* __restrict__ W,
                              const float* __restrict__ bias) {
    __shared__ float gs[CIN];
    int b = blockIdx.x;
    int t = threadIdx.x;       // 1024 threads

    if (t < CIN) {
        const float* pp = &g_part[b][t][0];
        float4 v0 = *(const float4*)(pp + 0);
        float4 v1 = *(const float4*)(pp + 4);
        float4 v2 = *(const float4*)(pp + 8);
        float4 v3 = *(const float4*)(pp + 12);
        gs[t] = ((v0.x + v0.y) + (v0.z + v0.w)) + ((v1.x + v1.y) + (v1.z + v1.w))
              + ((v2.x + v2.y) + (v2.z + v2.w)) + ((v3.x + v3.y) + (v3.z + v3.w));
    }
    __syncthreads();

    int o = t >> 2, q = t & 3;
    const float* wr = W + (size_t)o * CIN + q;
    float s = 0.f;
#pragma unroll 16
    for (int j = 0; j < 128; j++) s += wr[4 * j] * gs[q + 4 * j];
#pragma unroll
    for (int sh = 2; sh; sh >>= 1) s += __shfl_down_sync(0xffffffffu, s, sh, 4);
    if (q == 0)
        g_pooled[b * COUT + o] = (s + bias[o] * g_predsum[b]) * (1.0f / (float)HW);
}

// ---------------- memscan v4: Gram-matrix scan, barrier-free inner loop ---
__global__ void memscan_kernel(const int* __restrict__ epoch_p) {
    __shared__ float px[32 * 264];    // pooled rows
    __shared__ float Gs[32 * 33];     // Gram matrix
    __shared__ float sAl[32 * 33];    // final alpha coefficients
    __shared__ int   s_ptr;

    int t = threadIdx.x;              // 1024 threads
    float threshold = ((float)(*epoch_p) / 10.0f - 2.0f) * 0.4f / 13.0f + 0.3f;

    // load pooled rows (coalesced)
    for (int i = t; i < 2048; i += 1024) {
        int row = i >> 6, c4 = (i & 63) * 4;
        *(float4*)&px[row * 264 + c4] = *(const float4*)&g_pooled[row * 256 + c4];
    }
    __syncthreads();

    // Gram: thread (i = t>>5, j = t&31) computes G[i][j]
    {
        int i = t >> 5, j = t & 31;
        const float* xi = &px[i * 264];
        const float* xj = &px[j * 264];
        float s = 0.f;
#pragma unroll 8
        for (int c = 0; c < 256; c++) s += xi[c] * xj[c];
        Gs[i * 33 + j] = s;
    }
    __syncthreads();

    // warp 0: sequential scan on 32x32 coefficients, no barriers
    if (t < 32) {
        int p = t;
        float al[32];
#pragma unroll
        for (int j = 0; j < 32; j++) al[j] = 0.f;
        float m2 = 0.f;
        int ptr = 0;

        for (int i = 0; i < 32; i++) {
            float s = 0.f;
#pragma unroll
            for (int j = 0; j < 32; j++) s += al[j] * Gs[j * 33 + i];   // broadcast reads
            float Gii = Gs[i * 33 + i];
            float rxi = rsqrtf(Gii);
            float rm  = (m2 == 0.f) ? 1.0f : rsqrtf(m2);
            float sim = (p < ptr) ? s * rm * rxi : -INFINITY;

            float bv = sim; int bi = p;
#pragma unroll
            for (int o = 16; o; o >>= 1) {
                float ov = __shfl_xor_sync(0xffffffffu, bv, o);
                int   oi = __shfl_xor_sync(0xffffffffu, bi, o);
                if (ov > bv || (ov == bv && oi < bi)) { bv = ov; bi = oi; }
            }
            int ema = (ptr > 0) && (bv >= threshold);
            int idx = ema ? bi : ptr;
            if (p == idx) {
                if (ema) {
#pragma unroll
                    for (int j = 0; j < 32; j++)
                        al[j] = al[j] * 0.9f + ((j == i) ? 0.1f : 0.f);
                    m2 = 0.81f * m2 + 0.18f * s + 0.01f * Gii;
                } else {
#pragma unroll
                    for (int j = 0; j < 32; j++) al[j] = (j == i) ? 1.f : 0.f;
                    m2 = Gii;
                }
            }
            if (!ema) ptr++;
        }
#pragma unroll
        for (int j = 0; j < 32; j++) sAl[p * 33 + j] = al[j];
        if (p == 0) s_ptr = ptr;
    }
    __syncthreads();

    // reconstruct memory rows: mem[p] = sum_j alpha[p][j] * x_j
    int ptr = s_ptr;
    for (int idx = t; idx < ptr * 256; idx += 1024) {
        int p = idx >> 8, c = idx & 255;
        float v = 0.f;
#pragma unroll
        for (int j = 0; j < 32; j++) v += sAl[p * 33 + j] * px[j * 264 + c];
        g_mem[idx] = v;
    }
    if (t == 0) g_ptr = ptr;
}

// ---------------- proj GEMM (R11 known-good, unchanged) ------------------
__global__ __launch_bounds__(NTHREADS, 1)
void proj_mma(const float* __restrict__ feats,
              const float* __restrict__ preds,
              const float* __restrict__ W,
              const float* __restrict__ bias,
              float* __restrict__ out) {
    extern __shared__ char smem[];
    uint32_t* Au  = (uint32_t*)smem;
    float* Bs     = (float*)(smem + A_BYTES);
    float* pbuf   = (float*)(smem + PBUF_OFF);
    float* gacc   = (float*)(smem + GACC_OFF);

    int t = threadIdx.x, wid = t >> 5, lane = t & 31;
    int g = lane >> 2, tg = lane & 3;
    int b  = blockIdx.z;
    int m0 = blockIdx.y * BM;
    int n0 = blockIdx.x * BN;
    int warp_m = (wid >> 2) * 32;
    int warp_n = (wid & 3) * 64;
    bool do_g = (blockIdx.y == 0);

    const float* fb = feats + (size_t)b * CIN * HW + n0;
    uint32_t sB = smem_u32(Bs);

    if (do_g && t < 256) pbuf[t] = preds[(size_t)b * HW + n0 + t];

#pragma unroll
    for (int i = 0; i < 32; i++) {
        int c = t + i * NTHREADS;
        int row = c >> 7, col4 = (c & 127) * 4;
        float4 v = *(const float4*)(W + (size_t)(m0 + row) * CIN + col4);
        uint2 u;
        u.x = pack_h2(v.x, v.y);
        u.y = pack_h2(v.z, v.w);
        *(uint2*)(Au + row * A_STRIDE_U32 + (c & 127) * 2) = u;
    }

#pragma unroll
    for (int s = 0; s < NSTB - 1; s++) {
#pragma unroll
        for (int i = 0; i < 2; i++) {
            int c = t + i * NTHREADS;
            int row = c >> 6, col16 = c & 63;
            CP_ASYNC16(sB + s * B_STAGE_BYTES + row * (B_STRIDE * 4) + col16 * 16,
                       fb + (size_t)(s * BK + row) * HW + col16 * 4);
        }
        CP_COMMIT();
    }

    float acc[2][8][4];
#pragma unroll
    for (int mt = 0; mt < 2; mt++)
#pragma unroll
        for (int nt = 0; nt < 8; nt++)
#pragma unroll
            for (int q = 0; q < 4; q++) acc[mt][nt][q] = 0.f;

    for (int kt = 0; kt < NKT; kt++) {
        CP_WAIT(2);
        __syncthreads();
        if (kt + NSTB - 1 < NKT) {
            int s = (kt + NSTB - 1) & (NSTB - 1);
#pragma unroll
            for (int i = 0; i < 2; i++) {
                int c = t + i * NTHREADS;
                int row = c >> 6, col16 = c & 63;
                CP_ASYNC16(sB + s * B_STAGE_BYTES + row * (B_STRIDE * 4) + col16 * 16,
                           fb + (size_t)((kt + NSTB - 1) * BK + row) * HW + col16 * 4);
            }
        }
        CP_COMMIT();

        const float* BsS = Bs + (kt & (NSTB - 1)) * (BK * B_STRIDE);

        if (do_g && t < 256) {
            int kk = t >> 4, seg = t & 15;
            float s = 0.f;
#pragma unroll
            for (int j = 0; j < 16; j++)
                s += BsS[kk * B_STRIDE + seg + 16 * j] * pbuf[seg + 16 * j];
#pragma unroll
            for (int o = 8; o; o >>= 1) s += __shfl_down_sync(0xffffffffu, s, o, 16);
            if (seg == 0) gacc[kt * 16 + kk] = s;
        }

        uint32_t af[2][4];
#pragma unroll
        for (int mt = 0; mt < 2; mt++) {
            const uint32_t* ap = Au + (size_t)(warp_m + mt * 16 + g) * A_STRIDE_U32
                                 + kt * 8 + tg;
            af[mt][0] = ap[0];
            af[mt][1] = ap[8 * A_STRIDE_U32];
            af[mt][2] = ap[4];
            af[mt][3] = ap[8 * A_STRIDE_U32 + 4];
        }
        uint32_t bf[8][2];
        {
            const float* bk0 = BsS + (2 * tg) * B_STRIDE;
#pragma unroll
            for (int nt = 0; nt < 8; nt++) {
                int n = warp_n + nt * 8 + g;
                bf[nt][0] = pack_h2(bk0[n],                 bk0[B_STRIDE + n]);
                bf[nt][1] = pack_h2(bk0[8 * B_STRIDE + n],  bk0[9 * B_STRIDE + n]);
            }
        }
#pragma unroll
        for (int mt = 0; mt < 2; mt++)
#pragma unroll
            for (int nt = 0; nt < 8; nt++)
                MMA_F16(acc[mt][nt], af[mt], bf[nt]);
    }
    __syncthreads();

    if (do_g && t < 256) {
        g_part[b][t][blockIdx.x]       = gacc[t];
        g_part[b][t + 256][blockIdx.x] = gacc[t + 256];
    }

#pragma unroll
    for (int mt = 0; mt < 2; mt++) {
        int m = m0 + warp_m + mt * 16 + g;
        float bv0 = bias[m], bv1 = bias[m + 8];
        float* rowp = out + ((size_t)b * (2 * COUT) + m) * HW + n0 + warp_n + 2 * tg;
#pragma unroll
        for (int nt = 0; nt < 8; nt++) {
            *(float2*)(rowp + nt * 8)          = make_float2(acc[mt][nt][0] + bv0, acc[mt][nt][1] + bv0);
            *(float2*)(rowp + nt * 8 + 8 * HW) = make_float2(acc[mt][nt][2] + bv1, acc[mt][nt][3] + bv1);
        }
    }
}

// ---------------- attention v4: l-tile 256, lsm overlaid on stages -------
__global__ __launch_bounds__(256, 2)
void attn_mma(float* __restrict__ out) {
    extern __shared__ char smc[];
    float* memS = (float*)(smc + AT_MEMS_OFF);   // [32][260]
    float* stg  = (float*)(smc + AT_STG_OFF);    // 4 x [16][264]
    float* lsm  = stg;                           // [32][264] overlay (stages 0-1)

    int t = threadIdx.x, wid = t >> 5, lane = t & 31;
    int g = lane >> 2, tg = lane & 3;
    int b = blockIdx.y, l0 = blockIdx.x * AT_L;
    int ptr = g_ptr;

    for (int idx = t; idx < 32 * 256; idx += 256) {
        int p = idx >> 8, c = idx & 255;
        memS[p * MS_STRIDE + c] = (p < ptr) ? g_mem[idx] : 0.f;
    }

    const float* proj = out + (size_t)b * (2 * COUT) * HW;
    float* aug = out + (size_t)b * (2 * COUT) * HW + (size_t)COUT * HW + l0;
    uint32_t sStg = smem_u32(stg);

#define AT_LOAD(sidx, ktile) do {                                              \
    _Pragma("unroll")                                                          \
    for (int i = 0; i < 4; i++) {                                              \
        int c = t + i * 256;                                                   \
        int r = c >> 6, c16 = c & 63;                                          \
        CP_ASYNC16(sStg + (sidx) * AT_STAGE_BYTES + r * (LS_STRIDE * 4) + c16 * 16, \
                   proj + (size_t)((ktile) * 16 + r) * HW + l0 + c16 * 4);     \
    } } while (0)

    AT_LOAD(0, 0); CP_COMMIT();
    AT_LOAD(1, 1); CP_COMMIT();
    AT_LOAD(2, 2); CP_COMMIT();

    // ---- phase 1: logit[p][l] = mem @ proj, warp covers 32 l-cols ----
    float accl[2][4][4];
#pragma unroll
    for (int mt = 0; mt < 2; mt++)
#pragma unroll
        for (int nt = 0; nt < 4; nt++)
#pragma unroll
            for (int q = 0; q < 4; q++) accl[mt][nt][q] = 0.f;
    int n0w = wid * 32;

    for (int kt = 0; kt < 16; kt++) {
        CP_WAIT(2);
        __syncthreads();
        if (kt + 3 < 16) AT_LOAD((kt + 3) & 3, kt + 3);
        CP_COMMIT();

        const float* BsS = stg + (kt & 3) * (16 * LS_STRIDE);
#pragma unroll
        for (int kk = 0; kk < 2; kk++) {
            int kc = kt * 16 + kk * 8;
            uint32_t af[2][4];
#pragma unroll
            for (int mt = 0; mt < 2; mt++) {
                const float* ap = memS + (mt * 16 + g) * MS_STRIDE + kc + tg;
                af[mt][0] = f2tf32(ap[0]);
                af[mt][1] = f2tf32(ap[8 * MS_STRIDE]);
                af[mt][2] = f2tf32(ap[4]);
                af[mt][3] = f2tf32(ap[8 * MS_STRIDE + 4]);
            }
            uint32_t bf[4][2];
#pragma unroll
            for (int nt = 0; nt < 4; nt++) {
                const float* bp = BsS + (kk * 8 + tg) * LS_STRIDE + n0w + nt * 8 + g;
                bf[nt][0] = f2tf32(bp[0]);
                bf[nt][1] = f2tf32(bp[4 * LS_STRIDE]);
            }
#pragma unroll
            for (int mt = 0; mt < 2; mt++)
#pragma unroll
                for (int nt = 0; nt < 4; nt++)
                    MMA_TF32(accl[mt][nt], af[mt], bf[nt]);
        }
    }
    __syncthreads();   // all stage reads done; lsm overlay now safe
#pragma unroll
    for (int mt = 0; mt < 2; mt++)
#pragma unroll
        for (int nt = 0; nt < 4; nt++) {
            int p = mt * 16 + g;
            int l = n0w + nt * 8 + 2 * tg;
            *(float2*)&lsm[p * LS_STRIDE + l]       = make_float2(accl[mt][nt][0], accl[mt][nt][1]);
            *(float2*)&lsm[(p + 8) * LS_STRIDE + l] = make_float2(accl[mt][nt][2], accl[mt][nt][3]);
        }
    __syncthreads();

    // ---- phase 2: softmax over valid slots (256 threads = 256 cols) ----
    {
        float mx = -INFINITY;
        for (int p = 0; p < ptr; p++) mx = fmaxf(mx, lsm[p * LS_STRIDE + t]);
        float ss = 0.f;
        for (int p = 0; p < ptr; p++) {
            float e = expf(lsm[p * LS_STRIDE + t] - mx);
            lsm[p * LS_STRIDE + t] = e;
            ss += e;
        }
        float inv = 1.0f / ss;
        for (int p = 0; p < ptr; p++) lsm[p * LS_STRIDE + t] *= inv;
        for (int p = ptr; p < 32; p++) lsm[p * LS_STRIDE + t] = 0.f;
    }
    __syncthreads();

    // ---- phase 3: aug[c][l] = memS^T @ attn ----
    int m0w = wid * 32;
#pragma unroll
    for (int nh = 0; nh < 4; nh++) {
        float acca[2][8][4];
#pragma unroll
        for (int mt = 0; mt < 2; mt++)
#pragma unroll
            for (int nt = 0; nt < 8; nt++)
#pragma unroll
                for (int q = 0; q < 4; q++) acca[mt][nt][q] = 0.f;
#pragma unroll
        for (int ks = 0; ks < 4; ks++) {
            uint32_t af[2][4];
#pragma unroll
            for (int mt = 0; mt < 2; mt++) {
                const float* ap = memS + (ks * 8 + tg) * MS_STRIDE + m0w + mt * 16 + g;
                af[mt][0] = f2tf32(ap[0]);
                af[mt][1] = f2tf32(ap[8]);
                af[mt][2] = f2tf32(ap[4 * MS_STRIDE]);
                af[mt][3] = f2tf32(ap[4 * MS_STRIDE + 8]);
            }
            uint32_t bf[8][2];
#pragma unroll
            for (int nt = 0; nt < 8; nt++) {
                const float* bp = lsm + (ks * 8 + tg) * LS_STRIDE + nh * 64 + nt * 8 + g;
                bf[nt][0] = f2tf32(bp[0]);
                bf[nt][1] = f2tf32(bp[4 * LS_STRIDE]);
            }
#pragma unroll
            for (int mt = 0; mt < 2; mt++)
#pragma unroll
                for (int nt = 0; nt < 8; nt++)
                    MMA_TF32(acca[mt][nt], af[mt], bf[nt]);
        }
#pragma unroll
        for (int mt = 0; mt < 2; mt++) {
            int c = m0w + mt * 16 + g;
            float* r0 = aug + (size_t)c * HW + nh * 64 + 2 * tg;
            float* r1 = r0 + (size_t)8 * HW;
#pragma unroll
            for (int nt = 0; nt < 8; nt++) {
                *(float2*)(r0 + nt * 8) = make_float2(acca[mt][nt][0], acca[mt][nt][1]);
                *(float2*)(r1 + nt * 8) = make_float2(acca[mt][nt][2], acca[mt][nt][3]);
            }
        }
    }
#undef AT_LOAD
}

// ---------------- launch --------------------------------------------------
extern "C" void kernel_launch(void* const* d_in, const int* in_sizes, int n_in,
                              void* d_out, int out_size) {
    const float* feats = (const float*)d_in[0];
    const float* preds = (const float*)d_in[1];
    const float* W     = (const float*)d_in[2];
    const float* bias  = (const float*)d_in[3];
    const int*   epoch = (const int*)d_in[4];
    float* out = (float*)d_out;

    cudaFuncSetAttribute(proj_mma, cudaFuncAttributeMaxDynamicSharedMemorySize, SMEM_TOTAL);
    cudaFuncSetAttribute(attn_mma, cudaFuncAttributeMaxDynamicSharedMemorySize, AT_SMEM_TOTAL);

    predsum_kernel<<<BATCH, 256>>>(preds);
    proj_mma<<<dim3(NXT, COUT / BM, BATCH), NTHREADS, SMEM_TOTAL>>>(feats, preds, W, bias, out);
    pooled_kernel<<<BATCH, 1024>>>(W, bias);
    memscan_kernel<<<1, 1024>>>(epoch);
    attn_mma<<<dim3(HW / AT_L, BATCH), 256, AT_SMEM_TOTAL>>>(out);
}

// round 13
// speedup vs baseline: 1.3038x; 1.0045x over previous
#include <cuda_runtime.h>
#include <cuda_fp16.h>
#include <math.h>
#include <stdint.h>

#define HW    4096
#define CIN   512
#define COUT  256
#define BATCH 32

// ---- proj GEMM tiling (R11/R12 known-good) ----
#define BM 128
#define BN 256
#define BK 16
#define NKT (CIN / BK)
#define NSTB 4
#define NTHREADS 512
#define NXT (HW / BN)
#define A_STRIDE_U32 260
#define B_STRIDE 268
#define A_BYTES (BM * A_STRIDE_U32 * 4)
#define B_STAGE_BYTES (BK * B_STRIDE * 4)
#define PBUF_OFF (A_BYTES + NSTB * B_STAGE_BYTES)
#define GACC_OFF (PBUF_OFF + 256 * 4)
#define SMEM_TOTAL (GACC_OFF + 512 * 4)             // 204800

// ---- attn v5 smem layout: fp16 fragments, l-tile 256 ----
#define AT_L 256
#define MSH_STRIDE 132          // u32 (c-pair) stride for memSh
#define MTH_STRIDE 20           // u32 (p-pair) stride for memTh
#define LS_STRIDE 268           // fp32 stride for stages / lsm
#define AT_MEMSH_OFF 0
#define AT_MEMTH_OFF (32 * MSH_STRIDE * 4)              // 16896
#define AT_STG_OFF   (AT_MEMTH_OFF + 256 * MTH_STRIDE * 4) // 37376
#define AT_STAGE_BYTES (16 * LS_STRIDE * 4)             // 17152
#define AT_SMEM_TOTAL (AT_STG_OFF + 4 * AT_STAGE_BYTES) // 105984 -> 2 CTAs/SM

// ---------------- device scratch ----------------
__device__ float g_part[BATCH][CIN][NXT];
__device__ float g_predsum[BATCH];
__device__ float g_pooled[BATCH * COUT];
__device__ float g_G[32 * 32];
__device__ float g_alpha[32 * 33];
__device__ float g_mem[BATCH * COUT];
__device__ int   g_ptr;

__device__ __forceinline__ float warp_sum(float v) {
#pragma unroll
    for (int o = 16; o; o >>= 1) v += __shfl_down_sync(0xffffffffu, v, o);
    return v;
}
__device__ __forceinline__ uint32_t smem_u32(const void* p) {
    uint32_t a;
    asm("{ .reg .u64 t; cvta.to.shared.u64 t, %1; cvt.u32.u64 %0, t; }" : "=r"(a) : "l"(p));
    return a;
}
__device__ __forceinline__ uint32_t pack_h2(float lo, float hi) {
    __half2 h = __floats2half2_rn(lo, hi);
    return *(uint32_t*)&h;
}
#define CP_ASYNC16(saddr, gaddr) \
    asm volatile("cp.async.cg.shared.global [%0], [%1], 16;" :: "r"(saddr), "l"(gaddr))
#define CP_COMMIT()   asm volatile("cp.async.commit_group;" ::: "memory")
#define CP_WAIT(n)    asm volatile("cp.async.wait_group %0;" :: "n"(n) : "memory")

#define MMA_F16(c, a, bf) \
    asm volatile("mma.sync.aligned.m16n8k16.row.col.f32.f16.f16.f32 " \
        "{%0,%1,%2,%3}, {%4,%5,%6,%7}, {%8,%9}, {%0,%1,%2,%3};" \
        : "+f"((c)[0]), "+f"((c)[1]), "+f"((c)[2]), "+f"((c)[3]) \
        : "r"((a)[0]), "r"((a)[1]), "r"((a)[2]), "r"((a)[3]), \
          "r"((bf)[0]), "r"((bf)[1]))

// ---------------- predsum ----------------
__global__ void predsum_kernel(const float* __restrict__ preds) {
    int b = blockIdx.x;
    const float* pr = preds + (size_t)b * HW;
    int t = threadIdx.x;
    float s = 0.f;
    for (int i = t; i < HW; i += 256) s += pr[i];
    s = warp_sum(s);
    __shared__ float red[8];
    if ((t & 31) == 0) red[t >> 5] = s;
    __syncthreads();
    if (t == 0) {
        float tt = 0.f;
#pragma unroll
        for (int j = 0; j < 8; j++) tt += red[j];
        g_predsum[b] = tt;
    }
}

// ---------------- pooled v2 (R11) ----------------
__global__ void pooled_kernel(const float* __restrict__ W,
                              const float* __restrict__ bias) {
    __shared__ float gs[CIN];
    int b = blockIdx.x;
    int t = threadIdx.x;

    if (t < CIN) {
        const float* pp = &g_part[b][t][0];
        float4 v0 = *(const float4*)(pp + 0);
        float4 v1 = *(const float4*)(pp + 4);
        float4 v2 = *(const float4*)(pp + 8);
        float4 v3 = *(const float4*)(pp + 12);
        gs[t] = ((v0.x + v0.y) + (v0.z + v0.w)) + ((v1.x + v1.y) + (v1.z + v1.w))
              + ((v2.x + v2.y) + (v2.z + v2.w)) + ((v3.x + v3.y) + (v3.z + v3.w));
    }
    __syncthreads();

    int o = t >> 2, q = t & 3;
    const float* wr = W + (size_t)o * CIN + q;
    float s = 0.f;
#pragma unroll 16
    for (int j = 0; j < 128; j++) s += wr[4 * j] * gs[q + 4 * j];
#pragma unroll
    for (int sh = 2; sh; sh >>= 1) s += __shfl_down_sync(0xffffffffu, s, sh, 4);
    if (q == 0)
        g_pooled[b * COUT + o] = (s + bias[o] * g_predsum[b]) * (1.0f / (float)HW);
}

// ---------------- gram: G[i][j] = <x_i, x_j>, all-SM parallel -------------
__global__ void gram_kernel() {
    __shared__ float xs[256];
    int i = blockIdx.x;
    int t = threadIdx.x, w = t >> 5, lane = t & 31;
    xs[t] = g_pooled[i * 256 + t];
    __syncthreads();
#pragma unroll
    for (int jj = 0; jj < 4; jj++) {
        int j = w * 4 + jj;
        const float* xj = &g_pooled[j * 256];
        float s = 0.f;
#pragma unroll
        for (int k = 0; k < 8; k++) s += xs[lane + 32 * k] * xj[lane + 32 * k];
        s = warp_sum(s);
        if (lane == 0) g_G[i * 32 + j] = s;
    }
}

// ---------------- scan: the truly sequential recurrence, 1 warp ----------
__global__ void scan_kernel(const int* __restrict__ epoch_p) {
    __shared__ float Gs[32 * 33];
    int p = threadIdx.x;  // 32 threads
    float threshold = ((float)(*epoch_p) / 10.0f - 2.0f) * 0.4f / 13.0f + 0.3f;

    for (int j = 0; j < 32; j++) Gs[j * 33 + p] = g_G[j * 32 + p];
    __syncwarp();

    float al[32];
#pragma unroll
    for (int j = 0; j < 32; j++) al[j] = 0.f;
    float m2 = 0.f;
    int ptr = 0;

    for (int i = 0; i < 32; i++) {
        float s = 0.f;
#pragma unroll
        for (int j = 0; j < 32; j++) s += al[j] * Gs[j * 33 + i];
        float Gii = Gs[i * 33 + i];
        float rxi = rsqrtf(Gii);
        float rm  = (m2 == 0.f) ? 1.0f : rsqrtf(m2);
        float sim = (p < ptr) ? s * rm * rxi : -INFINITY;

        float bv = sim; int bi = p;
#pragma unroll
        for (int o = 16; o; o >>= 1) {
            float ov = __shfl_xor_sync(0xffffffffu, bv, o);
            int   oi = __shfl_xor_sync(0xffffffffu, bi, o);
            if (ov > bv || (ov == bv && oi < bi)) { bv = ov; bi = oi; }
        }
        int ema = (ptr > 0) && (bv >= threshold);
        int idx = ema ? bi : ptr;
        if (p == idx) {
            if (ema) {
#pragma unroll
                for (int j = 0; j < 32; j++)
                    al[j] = al[j] * 0.9f + ((j == i) ? 0.1f : 0.f);
                m2 = 0.81f * m2 + 0.18f * s + 0.01f * Gii;
            } else {
#pragma unroll
                for (int j = 0; j < 32; j++) al[j] = (j == i) ? 1.f : 0.f;
                m2 = Gii;
            }
        }
        if (!ema) ptr++;
    }
#pragma unroll
    for (int j = 0; j < 32; j++) g_alpha[p * 33 + j] = al[j];
    if (p == 0) g_ptr = ptr;
}

// ---------------- recon: mem[p] = alpha[p] @ X, parallel ------------------
__global__ void recon_kernel() {
    __shared__ float als[32];
    int p = blockIdx.x;
    int t = threadIdx.x;
    if (t < 32) als[t] = g_alpha[p * 33 + t];
    __syncthreads();
    if (p >= g_ptr) return;
    float v = 0.f;
#pragma unroll
    for (int j = 0; j < 32; j++) v += als[j] * g_pooled[j * 256 + t];
    g_mem[p * 256 + t] = v;
}

// ---------------- proj GEMM (R11/R12 known-good, unchanged) --------------
__global__ __launch_bounds__(NTHREADS, 1)
void proj_mma(const float* __restrict__ feats,
              const float* __restrict__ preds,
              const float* __restrict__ W,
              const float* __restrict__ bias,
              float* __restrict__ out) {
    extern __shared__ char smem[];
    uint32_t* Au  = (uint32_t*)smem;
    float* Bs     = (float*)(smem + A_BYTES);
    float* pbuf   = (float*)(smem + PBUF_OFF);
    float* gacc   = (float*)(smem + GACC_OFF);

    int t = threadIdx.x, wid = t >> 5, lane = t & 31;
    int g = lane >> 2, tg = lane & 3;
    int b  = blockIdx.z;
    int m0 = blockIdx.y * BM;
    int n0 = blockIdx.x * BN;
    int warp_m = (wid >> 2) * 32;
    int warp_n = (wid & 3) * 64;
    bool do_g = (blockIdx.y == 0);

    const float* fb = feats + (size_t)b * CIN * HW + n0;
    uint32_t sB = smem_u32(Bs);

    if (do_g && t < 256) pbuf[t] = preds[(size_t)b * HW + n0 + t];

#pragma unroll
    for (int i = 0; i < 32; i++) {
        int c = t + i * NTHREADS;
        int row = c >> 7, col4 = (c & 127) * 4;
        float4 v = *(const float4*)(W + (size_t)(m0 + row) * CIN + col4);
        uint2 u;
        u.x = pack_h2(v.x, v.y);
        u.y = pack_h2(v.z, v.w);
        *(uint2*)(Au + row * A_STRIDE_U32 + (c & 127) * 2) = u;
    }

#pragma unroll
    for (int s = 0; s < NSTB - 1; s++) {
#pragma unroll
        for (int i = 0; i < 2; i++) {
            int c = t + i * NTHREADS;
            int row = c >> 6, col16 = c & 63;
            CP_ASYNC16(sB + s * B_STAGE_BYTES + row * (B_STRIDE * 4) + col16 * 16,
                       fb + (size_t)(s * BK + row) * HW + col16 * 4);
        }
        CP_COMMIT();
    }

    float acc[2][8][4];
#pragma unroll
    for (int mt = 0; mt < 2; mt++)
#pragma unroll
        for (int nt = 0; nt < 8; nt++)
#pragma unroll
            for (int q = 0; q < 4; q++) acc[mt][nt][q] = 0.f;

    for (int kt = 0; kt < NKT; kt++) {
        CP_WAIT(2);
        __syncthreads();
        if (kt + NSTB - 1 < NKT) {
            int s = (kt + NSTB - 1) & (NSTB - 1);
#pragma unroll
            for (int i = 0; i < 2; i++) {
                int c = t + i * NTHREADS;
                int row = c >> 6, col16 = c & 63;
                CP_ASYNC16(sB + s * B_STAGE_BYTES + row * (B_STRIDE * 4) + col16 * 16,
                           fb + (size_t)((kt + NSTB - 1) * BK + row) * HW + col16 * 4);
            }
        }
        CP_COMMIT();

        const float* BsS = Bs + (kt & (NSTB - 1)) * (BK * B_STRIDE);

        if (do_g && t < 256) {
            int kk = t >> 4, seg = t & 15;
            float s = 0.f;
#pragma unroll
            for (int j = 0; j < 16; j++)
                s += BsS[kk * B_STRIDE + seg + 16 * j] * pbuf[seg + 16 * j];
#pragma unroll
            for (int o = 8; o; o >>= 1) s += __shfl_down_sync(0xffffffffu, s, o, 16);
            if (seg == 0) gacc[kt * 16 + kk] = s;
        }

        uint32_t af[2][4];
#pragma unroll
        for (int mt = 0; mt < 2; mt++) {
            const uint32_t* ap = Au + (size_t)(warp_m + mt * 16 + g) * A_STRIDE_U32
                                 + kt * 8 + tg;
            af[mt][0] = ap[0];
            af[mt][1] = ap[8 * A_STRIDE_U32];
            af[mt][2] = ap[4];
            af[mt][3] = ap[8 * A_STRIDE_U32 + 4];
        }
        uint32_t bf[8][2];
        {
            const float* bk0 = BsS + (2 * tg) * B_STRIDE;
#pragma unroll
            for (int nt = 0; nt < 8; nt++) {
                int n = warp_n + nt * 8 + g;
                bf[nt][0] = pack_h2(bk0[n],                 bk0[B_STRIDE + n]);
                bf[nt][1] = pack_h2(bk0[8 * B_STRIDE + n],  bk0[9 * B_STRIDE + n]);
            }
        }
#pragma unroll
        for (int mt = 0; mt < 2; mt++)
#pragma unroll
            for (int nt = 0; nt < 8; nt++)
                MMA_F16(acc[mt][nt], af[mt], bf[nt]);
    }
    __syncthreads();

    if (do_g && t < 256) {
        g_part[b][t][blockIdx.x]       = gacc[t];
        g_part[b][t + 256][blockIdx.x] = gacc[t + 256];
    }

#pragma unroll
    for (int mt = 0; mt < 2; mt++) {
        int m = m0 + warp_m + mt * 16 + g;
        float bv0 = bias[m], bv1 = bias[m + 8];
        float* rowp = out + ((size_t)b * (2 * COUT) + m) * HW + n0 + warp_n + 2 * tg;
#pragma unroll
        for (int nt = 0; nt < 8; nt++) {
            *(float2*)(rowp + nt * 8)          = make_float2(acc[mt][nt][0] + bv0, acc[mt][nt][1] + bv0);
            *(float2*)(rowp + nt * 8 + 8 * HW) = make_float2(acc[mt][nt][2] + bv1, acc[mt][nt][3] + bv1);
        }
    }
}

// ---------------- attention v5: fp16 MMA everywhere -----------------------
__global__ __launch_bounds__(256, 2)
void attn_mma(float* __restrict__ out) {
    extern __shared__ char smc[];
    uint32_t* memSh = (uint32_t*)(smc + AT_MEMSH_OFF);  // [32][132] c-pairs
    uint32_t* memTh = (uint32_t*)(smc + AT_MEMTH_OFF);  // [256][20] p-pairs
    float* stg = (float*)(smc + AT_STG_OFF);            // 4 x [16][268]
    float* lsm = stg;                                   // [32][268] overlay

    int t = threadIdx.x, wid = t >> 5, lane = t & 31;
    int g = lane >> 2, tg = lane & 3;
    int b = blockIdx.y, l0 = blockIdx.x * AT_L;
    int ptr = g_ptr;

    // pack codebook into both fp16 orientations
    for (int idx = t; idx < 32 * 128; idx += 256) {        // c-pairs
        int p = idx >> 7, cp = idx & 127;
        uint32_t v = 0;
        if (p < ptr) v = pack_h2(g_mem[p * 256 + 2 * cp], g_mem[p * 256 + 2 * cp + 1]);
        memSh[p * MSH_STRIDE + cp] = v;
    }
    for (int idx = t; idx < 256 * 16; idx += 256) {        // p-pairs
        int c = idx & 255, pp = idx >> 8;
        float lo = (2 * pp     < ptr) ? g_mem[(2 * pp) * 256 + c]     : 0.f;
        float hi = (2 * pp + 1 < ptr) ? g_mem[(2 * pp + 1) * 256 + c] : 0.f;
        memTh[c * MTH_STRIDE + pp] = pack_h2(lo, hi);
    }

    const float* proj = out + (size_t)b * (2 * COUT) * HW;
    float* aug = out + (size_t)b * (2 * COUT) * HW + (size_t)COUT * HW + l0;
    uint32_t sStg = smem_u32(stg);

#define AT_LOAD(sidx, ktile) do {                                              \
    _Pragma("unroll")                                                          \
    for (int i = 0; i < 4; i++) {                                              \
        int c = t + i * 256;                                                   \
        int r = c >> 6, c16 = c & 63;                                          \
        CP_ASYNC16(sStg + (sidx) * AT_STAGE_BYTES + r * (LS_STRIDE * 4) + c16 * 16, \
                   proj + (size_t)((ktile) * 16 + r) * HW + l0 + c16 * 4);     \
    } } while (0)

    AT_LOAD(0, 0); CP_COMMIT();
    AT_LOAD(1, 1); CP_COMMIT();
    AT_LOAD(2, 2); CP_COMMIT();

    // ---- phase 1: logit[p][l], fp16 mma, 8 MMAs/kt ----
    float accl[2][4][4];
#pragma unroll
    for (int mt = 0; mt < 2; mt++)
#pragma unroll
        for (int nt = 0; nt < 4; nt++)
#pragma unroll
            for (int q = 0; q < 4; q++) accl[mt][nt][q] = 0.f;
    int n0w = wid * 32;

    for (int kt = 0; kt < 16; kt++) {
        CP_WAIT(2);
        __syncthreads();
        if (kt + 3 < 16) AT_LOAD((kt + 3) & 3, kt + 3);
        CP_COMMIT();

        const float* BsS = stg + (kt & 3) * (16 * LS_STRIDE);
        uint32_t af[2][4];
#pragma unroll
        for (int mt = 0; mt < 2; mt++) {
            const uint32_t* ap = memSh + (mt * 16 + g) * MSH_STRIDE + kt * 8 + tg;
            af[mt][0] = ap[0];
            af[mt][1] = ap[8 * MSH_STRIDE];
            af[mt][2] = ap[4];
            af[mt][3] = ap[8 * MSH_STRIDE + 4];
        }
        uint32_t bf[4][2];
        {
            const float* bk0 = BsS + (2 * tg) * LS_STRIDE;
#pragma unroll
            for (int nt = 0; nt < 4; nt++) {
                int n = n0w + nt * 8 + g;
                bf[nt][0] = pack_h2(bk0[n],                  bk0[LS_STRIDE + n]);
                bf[nt][1] = pack_h2(bk0[8 * LS_STRIDE + n],  bk0[9 * LS_STRIDE + n]);
            }
        }
#pragma unroll
        for (int mt = 0; mt < 2; mt++)
#pragma unroll
            for (int nt = 0; nt < 4; nt++)
                MMA_F16(accl[mt][nt], af[mt], bf[nt]);
    }
    __syncthreads();   // all stage reads done; lsm overlay safe
#pragma unroll
    for (int mt = 0; mt < 2; mt++)
#pragma unroll
        for (int nt = 0; nt < 4; nt++) {
            int p = mt * 16 + g;
            int l = n0w + nt * 8 + 2 * tg;
            *(float2*)&lsm[p * LS_STRIDE + l]       = make_float2(accl[mt][nt][0], accl[mt][nt][1]);
            *(float2*)&lsm[(p + 8) * LS_STRIDE + l] = make_float2(accl[mt][nt][2], accl[mt][nt][3]);
        }
    __syncthreads();

    // ---- phase 2: softmax over valid slots ----
    {
        float mx = -INFINITY;
        for (int p = 0; p < ptr; p++) mx = fmaxf(mx, lsm[p * LS_STRIDE + t]);
        float ss = 0.f;
        for (int p = 0; p < ptr; p++) {
            float e = expf(lsm[p * LS_STRIDE + t] - mx);
            lsm[p * LS_STRIDE + t] = e;
            ss += e;
        }
        float inv = 1.0f / ss;
        for (int p = 0; p < ptr; p++) lsm[p * LS_STRIDE + t] *= inv;
        for (int p = ptr; p < 32; p++) lsm[p * LS_STRIDE + t] = 0.f;
    }
    __syncthreads();

    // ---- phase 3: aug = mem^T @ attn, fp16 mma ----
    int m0w = wid * 32;
#pragma unroll
    for (int nh = 0; nh < 4; nh++) {
        float acca[2][8][4];
#pragma unroll
        for (int mt = 0; mt < 2; mt++)
#pragma unroll
            for (int nt = 0; nt < 8; nt++)
#pragma unroll
                for (int q = 0; q < 4; q++) acca[mt][nt][q] = 0.f;
#pragma unroll
        for (int ks = 0; ks < 2; ks++) {
            uint32_t af[2][4];
#pragma unroll
            for (int mt = 0; mt < 2; mt++) {
                const uint32_t* ap = memTh + (m0w + mt * 16 + g) * MTH_STRIDE + ks * 8 + tg;
                af[mt][0] = ap[0];
                af[mt][1] = ap[8 * MTH_STRIDE];
                af[mt][2] = ap[4];
                af[mt][3] = ap[8 * MTH_STRIDE + 4];
            }
            uint32_t bf[8][2];
            {
                const float* bk0 = lsm + (ks * 16 + 2 * tg) * LS_STRIDE;
#pragma unroll
                for (int nt = 0; nt < 8; nt++) {
                    int n = nh * 64 + nt * 8 + g;
                    bf[nt][0] = pack_h2(bk0[n],                  bk0[LS_STRIDE + n]);
                    bf[nt][1] = pack_h2(bk0[8 * LS_STRIDE + n],  bk0[9 * LS_STRIDE + n]);
                }
            }
#pragma unroll
            for (int mt = 0; mt < 2; mt++)
#pragma unroll
                for (int nt = 0; nt < 8; nt++)
                    MMA_F16(acca[mt][nt], af[mt], bf[nt]);
        }
#pragma unroll
        for (int mt = 0; mt < 2; mt++) {
            int c = m0w + mt * 16 + g;
            float* r0 = aug + (size_t)c * HW + nh * 64 + 2 * tg;
            float* r1 = r0 + (size_t)8 * HW;
#pragma unroll
            for (int nt = 0; nt < 8; nt++) {
                *(float2*)(r0 + nt * 8) = make_float2(acca[mt][nt][0], acca[mt][nt][1]);
                *(float2*)(r1 + nt * 8) = make_float2(acca[mt][nt][2], acca[mt][nt][3]);
            }
        }
    }
#undef AT_LOAD
}

// ---------------- launch --------------------------------------------------
extern "C" void kernel_launch(void* const* d_in, const int* in_sizes, int n_in,
                              void* d_out, int out_size) {
    const float* feats = (const float*)d_in[0];
    const float* preds = (const float*)d_in[1];
    const float* W     = (const float*)d_in[2];
    const float* bias  = (const float*)d_in[3];
    const int*   epoch = (const int*)d_in[4];
    float* out = (float*)d_out;

    cudaFuncSetAttribute(proj_mma, cudaFuncAttributeMaxDynamicSharedMemorySize, SMEM_TOTAL);
    cudaFuncSetAttribute(attn_mma, cudaFuncAttributeMaxDynamicSharedMemorySize, AT_SMEM_TOTAL);

    predsum_kernel<<<BATCH, 256>>>(preds);
    proj_mma<<<dim3(NXT, COUT / BM, BATCH), NTHREADS, SMEM_TOTAL>>>(feats, preds, W, bias, out);
    pooled_kernel<<<BATCH, 1024>>>(W, bias);
    gram_kernel<<<32, 256>>>();
    scan_kernel<<<1, 32>>>(epoch);
    recon_kernel<<<32, 256>>>();
    attn_mma<<<dim3(HW / AT_L, BATCH), 256, AT_SMEM_TOTAL>>>(out);
}

// round 14
// speedup vs baseline: 1.3728x; 1.0529x over previous
#include <cuda_runtime.h>
#include <cuda_fp16.h>
#include <math.h>
#include <stdint.h>

#define HW    4096
#define CIN   512
#define COUT  256
#define BATCH 32

// ---- proj GEMM tiling (R11-R13 known-good) ----
#define BM 128
#define BN 256
#define BK 16
#define NKT (CIN / BK)
#define NSTB 4
#define NTHREADS 512
#define NXT (HW / BN)
#define A_STRIDE_U32 260
#define B_STRIDE 268
#define A_BYTES (BM * A_STRIDE_U32 * 4)
#define B_STAGE_BYTES (BK * B_STRIDE * 4)
#define PBUF_OFF (A_BYTES + NSTB * B_STAGE_BYTES)
#define GACC_OFF (PBUF_OFF + 256 * 4)
#define SMEM_TOTAL (GACC_OFF + 512 * 4)             // 204800

// ---- attn v6: AT_L=1024, single wave, 5x8-row stages ----
#define AT_L 1024
#define LS_STRIDE 1028
#define NSTA 5
#define MSH_STRIDE 132
#define MTH_STRIDE 20
#define AT_MEMSH_OFF 0
#define AT_MEMTH_OFF (32 * MSH_STRIDE * 4)                  // 16896
#define AT_STG_OFF   (AT_MEMTH_OFF + 256 * MTH_STRIDE * 4)  // 37376
#define AT_STAGE_BYTES (8 * LS_STRIDE * 4)                  // 32896
#define AT_SMEM_TOTAL (AT_STG_OFF + NSTA * AT_STAGE_BYTES)  // 201856

// ---------------- device scratch ----------------
__device__ float g_part[BATCH][CIN][NXT];
__device__ float g_pooled[BATCH * COUT];
__device__ float g_G[32 * 32];
__device__ float g_alpha[32 * 33];
__device__ float g_mem[BATCH * COUT];
__device__ int   g_ptr;

__device__ __forceinline__ float warp_sum(float v) {
#pragma unroll
    for (int o = 16; o; o >>= 1) v += __shfl_down_sync(0xffffffffu, v, o);
    return v;
}
__device__ __forceinline__ uint32_t smem_u32(const void* p) {
    uint32_t a;
    asm("{ .reg .u64 t; cvta.to.shared.u64 t, %1; cvt.u32.u64 %0, t; }" : "=r"(a) : "l"(p));
    return a;
}
__device__ __forceinline__ uint32_t pack_h2(float lo, float hi) {
    __half2 h = __floats2half2_rn(lo, hi);
    return *(uint32_t*)&h;
}
#define CP_ASYNC16(saddr, gaddr) \
    asm volatile("cp.async.cg.shared.global [%0], [%1], 16;" :: "r"(saddr), "l"(gaddr))
#define CP_COMMIT()   asm volatile("cp.async.commit_group;" ::: "memory")
#define CP_WAIT(n)    asm volatile("cp.async.wait_group %0;" :: "n"(n) : "memory")

#define MMA_F16(c, a, bf) \
    asm volatile("mma.sync.aligned.m16n8k16.row.col.f32.f16.f16.f32 " \
        "{%0,%1,%2,%3}, {%4,%5,%6,%7}, {%8,%9}, {%0,%1,%2,%3};" \
        : "+f"((c)[0]), "+f"((c)[1]), "+f"((c)[2]), "+f"((c)[3]) \
        : "r"((a)[0]), "r"((a)[1]), "r"((a)[2]), "r"((a)[3]), \
          "r"((bf)[0]), "r"((bf)[1]))

// ---------------- pooled v3: predsum fused ----------------
__global__ void pooled_kernel(const float* __restrict__ preds,
                              const float* __restrict__ W,
                              const float* __restrict__ bias) {
    __shared__ float gs[CIN];
    __shared__ float red[32];
    __shared__ float s_ps;
    int b = blockIdx.x;
    int t = threadIdx.x, w = t >> 5, lane = t & 31;

    // predsum
    const float* pr = preds + (size_t)b * HW;
    float s = pr[t] + pr[t + 1024] + pr[t + 2048] + pr[t + 3072];
    s = warp_sum(s);
    if (lane == 0) red[w] = s;
    __syncthreads();
    if (t == 0) {
        float tt = 0.f;
#pragma unroll
        for (int j = 0; j < 32; j++) tt += red[j];
        s_ps = tt;
    }

    // phase A: reduce 16 contiguous partials per channel
    if (t < CIN) {
        const float* pp = &g_part[b][t][0];
        float4 v0 = *(const float4*)(pp + 0);
        float4 v1 = *(const float4*)(pp + 4);
        float4 v2 = *(const float4*)(pp + 8);
        float4 v3 = *(const float4*)(pp + 12);
        gs[t] = ((v0.x + v0.y) + (v0.z + v0.w)) + ((v1.x + v1.y) + (v1.z + v1.w))
              + ((v2.x + v2.y) + (v2.z + v2.w)) + ((v3.x + v3.y) + (v3.z + v3.w));
    }
    __syncthreads();

    // phase B: 4 threads per output channel
    int o = t >> 2, q = t & 3;
    const float* wr = W + (size_t)o * CIN + q;
    float sum = 0.f;
#pragma unroll 16
    for (int j = 0; j < 128; j++) sum += wr[4 * j] * gs[q + 4 * j];
#pragma unroll
    for (int sh = 2; sh; sh >>= 1) sum += __shfl_down_sync(0xffffffffu, sum, sh, 4);
    if (q == 0)
        g_pooled[b * COUT + o] = (sum + bias[o] * s_ps) * (1.0f / (float)HW);
}

// ---------------- gram (R13) ----------------
__global__ void gram_kernel() {
    __shared__ float xs[256];
    int i = blockIdx.x;
    int t = threadIdx.x, w = t >> 5, lane = t & 31;
    xs[t] = g_pooled[i * 256 + t];
    __syncthreads();
#pragma unroll
    for (int jj = 0; jj < 4; jj++) {
        int j = w * 4 + jj;
        const float* xj = &g_pooled[j * 256];
        float s = 0.f;
#pragma unroll
        for (int k = 0; k < 8; k++) s += xs[lane + 32 * k] * xj[lane + 32 * k];
        s = warp_sum(s);
        if (lane == 0) g_G[i * 32 + j] = s;
    }
}

// ---------------- scan (R13) ----------------
__global__ void scan_kernel(const int* __restrict__ epoch_p) {
    __shared__ float Gs[32 * 33];
    int p = threadIdx.x;
    float threshold = ((float)(*epoch_p) / 10.0f - 2.0f) * 0.4f / 13.0f + 0.3f;

    for (int j = 0; j < 32; j++) Gs[j * 33 + p] = g_G[j * 32 + p];
    __syncwarp();

    float al[32];
#pragma unroll
    for (int j = 0; j < 32; j++) al[j] = 0.f;
    float m2 = 0.f;
    int ptr = 0;

    for (int i = 0; i < 32; i++) {
        float s = 0.f;
#pragma unroll
        for (int j = 0; j < 32; j++) s += al[j] * Gs[j * 33 + i];
        float Gii = Gs[i * 33 + i];
        float rxi = rsqrtf(Gii);
        float rm  = (m2 == 0.f) ? 1.0f : rsqrtf(m2);
        float sim = (p < ptr) ? s * rm * rxi : -INFINITY;

        float bv = sim; int bi = p;
#pragma unroll
        for (int o = 16; o; o >>= 1) {
            float ov = __shfl_xor_sync(0xffffffffu, bv, o);
            int   oi = __shfl_xor_sync(0xffffffffu, bi, o);
            if (ov > bv || (ov == bv && oi < bi)) { bv = ov; bi = oi; }
        }
        int ema = (ptr > 0) && (bv >= threshold);
        int idx = ema ? bi : ptr;
        if (p == idx) {
            if (ema) {
#pragma unroll
                for (int j = 0; j < 32; j++)
                    al[j] = al[j] * 0.9f + ((j == i) ? 0.1f : 0.f);
                m2 = 0.81f * m2 + 0.18f * s + 0.01f * Gii;
            } else {
#pragma unroll
                for (int j = 0; j < 32; j++) al[j] = (j == i) ? 1.f : 0.f;
                m2 = Gii;
            }
        }
        if (!ema) ptr++;
    }
#pragma unroll
    for (int j = 0; j < 32; j++) g_alpha[p * 33 + j] = al[j];
    if (p == 0) g_ptr = ptr;
}

// ---------------- recon (R13) ----------------
__global__ void recon_kernel() {
    __shared__ float als[32];
    int p = blockIdx.x;
    int t = threadIdx.x;
    if (t < 32) als[t] = g_alpha[p * 33 + t];
    __syncthreads();
    if (p >= g_ptr) return;
    float v = 0.f;
#pragma unroll
    for (int j = 0; j < 32; j++) v += als[j] * g_pooled[j * 256 + t];
    g_mem[p * 256 + t] = v;
}

// ---------------- proj GEMM (R11-R13 known-good, unchanged) --------------
__global__ __launch_bounds__(NTHREADS, 1)
void proj_mma(const float* __restrict__ feats,
              const float* __restrict__ preds,
              const float* __restrict__ W,
              const float* __restrict__ bias,
              float* __restrict__ out) {
    extern __shared__ char smem[];
    uint32_t* Au  = (uint32_t*)smem;
    float* Bs     = (float*)(smem + A_BYTES);
    float* pbuf   = (float*)(smem + PBUF_OFF);
    float* gacc   = (float*)(smem + GACC_OFF);

    int t = threadIdx.x, wid = t >> 5, lane = t & 31;
    int g = lane >> 2, tg = lane & 3;
    int b  = blockIdx.z;
    int m0 = blockIdx.y * BM;
    int n0 = blockIdx.x * BN;
    int warp_m = (wid >> 2) * 32;
    int warp_n = (wid & 3) * 64;
    bool do_g = (blockIdx.y == 0);

    const float* fb = feats + (size_t)b * CIN * HW + n0;
    uint32_t sB = smem_u32(Bs);

    if (do_g && t < 256) pbuf[t] = preds[(size_t)b * HW + n0 + t];

#pragma unroll
    for (int i = 0; i < 32; i++) {
        int c = t + i * NTHREADS;
        int row = c >> 7, col4 = (c & 127) * 4;
        float4 v = *(const float4*)(W + (size_t)(m0 + row) * CIN + col4);
        uint2 u;
        u.x = pack_h2(v.x, v.y);
        u.y = pack_h2(v.z, v.w);
        *(uint2*)(Au + row * A_STRIDE_U32 + (c & 127) * 2) = u;
    }

#pragma unroll
    for (int s = 0; s < NSTB - 1; s++) {
#pragma unroll
        for (int i = 0; i < 2; i++) {
            int c = t + i * NTHREADS;
            int row = c >> 6, col16 = c & 63;
            CP_ASYNC16(sB + s * B_STAGE_BYTES + row * (B_STRIDE * 4) + col16 * 16,
                       fb + (size_t)(s * BK + row) * HW + col16 * 4);
        }
        CP_COMMIT();
    }

    float acc[2][8][4];
#pragma unroll
    for (int mt = 0; mt < 2; mt++)
#pragma unroll
        for (int nt = 0; nt < 8; nt++)
#pragma unroll
            for (int q = 0; q < 4; q++) acc[mt][nt][q] = 0.f;

    for (int kt = 0; kt < NKT; kt++) {
        CP_WAIT(2);
        __syncthreads();
        if (kt + NSTB - 1 < NKT) {
            int s = (kt + NSTB - 1) & (NSTB - 1);
#pragma unroll
            for (int i = 0; i < 2; i++) {
                int c = t + i * NTHREADS;
                int row = c >> 6, col16 = c & 63;
                CP_ASYNC16(sB + s * B_STAGE_BYTES + row * (B_STRIDE * 4) + col16 * 16,
                           fb + (size_t)((kt + NSTB - 1) * BK + row) * HW + col16 * 4);
            }
        }
        CP_COMMIT();

        const float* BsS = Bs + (kt & (NSTB - 1)) * (BK * B_STRIDE);

        if (do_g && t < 256) {
            int kk = t >> 4, seg = t & 15;
            float s = 0.f;
#pragma unroll
            for (int j = 0; j < 16; j++)
                s += BsS[kk * B_STRIDE + seg + 16 * j] * pbuf[seg + 16 * j];
#pragma unroll
            for (int o = 8; o; o >>= 1) s += __shfl_down_sync(0xffffffffu, s, o, 16);
            if (seg == 0) gacc[kt * 16 + kk] = s;
        }

        uint32_t af[2][4];
#pragma unroll
        for (int mt = 0; mt < 2; mt++) {
            const uint32_t* ap = Au + (size_t)(warp_m + mt * 16 + g) * A_STRIDE_U32
                                 + kt * 8 + tg;
            af[mt][0] = ap[0];
            af[mt][1] = ap[8 * A_STRIDE_U32];
            af[mt][2] = ap[4];
            af[mt][3] = ap[8 * A_STRIDE_U32 + 4];
        }
        uint32_t bf[8][2];
        {
            const float* bk0 = BsS + (2 * tg) * B_STRIDE;
#pragma unroll
            for (int nt = 0; nt < 8; nt++) {
                int n = warp_n + nt * 8 + g;
                bf[nt][0] = pack_h2(bk0[n],                 bk0[B_STRIDE + n]);
                bf[nt][1] = pack_h2(bk0[8 * B_STRIDE + n],  bk0[9 * B_STRIDE + n]);
            }
        }
#pragma unroll
        for (int mt = 0; mt < 2; mt++)
#pragma unroll
            for (int nt = 0; nt < 8; nt++)
                MMA_F16(acc[mt][nt], af[mt], bf[nt]);
    }
    __syncthreads();

    if (do_g && t < 256) {
        g_part[b][t][blockIdx.x]       = gacc[t];
        g_part[b][t + 256][blockIdx.x] = gacc[t + 256];
    }

#pragma unroll
    for (int mt = 0; mt < 2; mt++) {
        int m = m0 + warp_m + mt * 16 + g;
        float bv0 = bias[m], bv1 = bias[m + 8];
        float* rowp = out + ((size_t)b * (2 * COUT) + m) * HW + n0 + warp_n + 2 * tg;
#pragma unroll
        for (int nt = 0; nt < 8; nt++) {
            *(float2*)(rowp + nt * 8)          = make_float2(acc[mt][nt][0] + bv0, acc[mt][nt][1] + bv0);
            *(float2*)(rowp + nt * 8 + 8 * HW) = make_float2(acc[mt][nt][2] + bv1, acc[mt][nt][3] + bv1);
        }
    }
}

// ---------------- attention v6: AT_L=1024, single wave --------------------
__global__ __launch_bounds__(256, 1)
void attn_mma(float* __restrict__ out) {
    extern __shared__ char smc[];
    uint32_t* memSh = (uint32_t*)(smc + AT_MEMSH_OFF);  // [32][132] c-pairs
    uint32_t* memTh = (uint32_t*)(smc + AT_MEMTH_OFF);  // [256][20] p-pairs
    float* stg = (float*)(smc + AT_STG_OFF);            // 5 x [8][1028]
    float* lsm = stg;                                   // [32][1028] overlay

    int t = threadIdx.x, wid = t >> 5, lane = t & 31;
    int g = lane >> 2, tg = lane & 3;
    int b = blockIdx.y, l0 = blockIdx.x * AT_L;
    int ptr = g_ptr;

    // pack codebook into both fp16 orientations
    for (int idx = t; idx < 32 * 128; idx += 256) {
        int p = idx >> 7, cp = idx & 127;
        uint32_t v = 0;
        if (p < ptr) v = pack_h2(g_mem[p * 256 + 2 * cp], g_mem[p * 256 + 2 * cp + 1]);
        memSh[p * MSH_STRIDE + cp] = v;
    }
    for (int idx = t; idx < 256 * 16; idx += 256) {
        int c = idx & 255, pp = idx >> 8;
        float lo = (2 * pp     < ptr) ? g_mem[(2 * pp) * 256 + c]     : 0.f;
        float hi = (2 * pp + 1 < ptr) ? g_mem[(2 * pp + 1) * 256 + c] : 0.f;
        memTh[c * MTH_STRIDE + pp] = pack_h2(lo, hi);
    }

    const float* proj = out + (size_t)b * (2 * COUT) * HW;
    float* aug = out + (size_t)b * (2 * COUT) * HW + (size_t)COUT * HW + l0;
    uint32_t sStg = smem_u32(stg);

    // stage ss = 8 c-rows [ss*8, ss*8+8); 2048 16B-chunks per stage
#define AT_LOAD(buf, ss) do {                                                  \
    _Pragma("unroll")                                                          \
    for (int i = 0; i < 8; i++) {                                              \
        int c = t + i * 256;                                                   \
        int r = c >> 8, c16 = c & 255;                                         \
        CP_ASYNC16(sStg + (buf) * AT_STAGE_BYTES + r * (LS_STRIDE * 4) + c16 * 16, \
                   proj + (size_t)((ss) * 8 + r) * HW + l0 + c16 * 4);         \
    } } while (0)

    AT_LOAD(0, 0); CP_COMMIT();
    AT_LOAD(1, 1); CP_COMMIT();
    AT_LOAD(2, 2); CP_COMMIT();

    // ---- phase 1: logit[p][l], warp covers 128 l-cols ----
    float accl[2][16][4];
#pragma unroll
    for (int mt = 0; mt < 2; mt++)
#pragma unroll
        for (int nt = 0; nt < 16; nt++)
#pragma unroll
            for (int q = 0; q < 4; q++) accl[mt][nt][q] = 0.f;
    int n0w = wid * 128;

    for (int s = 0; s < 32; s++) {
        CP_WAIT(2);
        __syncthreads();
        if (s + 3 < 32) AT_LOAD((s + 3) % NSTA, s + 3);
        CP_COMMIT();

        if (s & 1) {
            int kt = s >> 1;
            uint32_t af[2][4];
#pragma unroll
            for (int mt = 0; mt < 2; mt++) {
                const uint32_t* ap = memSh + (mt * 16 + g) * MSH_STRIDE + kt * 8 + tg;
                af[mt][0] = ap[0];
                af[mt][1] = ap[8 * MSH_STRIDE];
                af[mt][2] = ap[4];
                af[mt][3] = ap[8 * MSH_STRIDE + 4];
            }
            const float* a0 = stg + ((s - 1) % NSTA) * (8 * LS_STRIDE) + (2 * tg) * LS_STRIDE;
            const float* b0 = stg + (s % NSTA) * (8 * LS_STRIDE) + (2 * tg) * LS_STRIDE;
#pragma unroll
            for (int nt = 0; nt < 16; nt++) {
                int n = n0w + nt * 8 + g;
                uint32_t bf[2];
                bf[0] = pack_h2(a0[n], a0[LS_STRIDE + n]);
                bf[1] = pack_h2(b0[n], b0[LS_STRIDE + n]);
                MMA_F16(accl[0][nt], af[0], bf);
                MMA_F16(accl[1][nt], af[1], bf);
            }
        }
    }
    __syncthreads();   // all stage reads done; lsm overlay safe
#pragma unroll
    for (int mt = 0; mt < 2; mt++)
#pragma unroll
        for (int nt = 0; nt < 16; nt++) {
            int p = mt * 16 + g;
            int l = n0w + nt * 8 + 2 * tg;
            *(float2*)&lsm[p * LS_STRIDE + l]       = make_float2(accl[mt][nt][0], accl[mt][nt][1]);
            *(float2*)&lsm[(p + 8) * LS_STRIDE + l] = make_float2(accl[mt][nt][2], accl[mt][nt][3]);
        }
    __syncthreads();

    // ---- phase 2: softmax; 256 threads x 4 cols ----
#pragma unroll
    for (int cc = 0; cc < 4; cc++) {
        int col = cc * 256 + t;
        float mx = -INFINITY;
        for (int p = 0; p < ptr; p++) mx = fmaxf(mx, lsm[p * LS_STRIDE + col]);
        float ss = 0.f;
        for (int p = 0; p < ptr; p++) {
            float e = expf(lsm[p * LS_STRIDE + col] - mx);
            lsm[p * LS_STRIDE + col] = e;
            ss += e;
        }
        float inv = 1.0f / ss;
        for (int p = 0; p < ptr; p++) lsm[p * LS_STRIDE + col] *= inv;
        for (int p = ptr; p < 32; p++) lsm[p * LS_STRIDE + col] = 0.f;
    }
    __syncthreads();

    // ---- phase 3: aug = mem^T @ attn ----
    int m0w = wid * 32;
#pragma unroll
    for (int nh = 0; nh < 16; nh++) {
        float acca[2][8][4];
#pragma unroll
        for (int mt = 0; mt < 2; mt++)
#pragma unroll
            for (int nt = 0; nt < 8; nt++)
#pragma unroll
                for (int q = 0; q < 4; q++) acca[mt][nt][q] = 0.f;
#pragma unroll
        for (int ks = 0; ks < 2; ks++) {
            uint32_t af[2][4];
#pragma unroll
            for (int mt = 0; mt < 2; mt++) {
                const uint32_t* ap = memTh + (m0w + mt * 16 + g) * MTH_STRIDE + ks * 8 + tg;
                af[mt][0] = ap[0];
                af[mt][1] = ap[8 * MTH_STRIDE];
                af[mt][2] = ap[4];
                af[mt][3] = ap[8 * MTH_STRIDE + 4];
            }
            const float* bk0 = lsm + (ks * 16 + 2 * tg) * LS_STRIDE;
            uint32_t bf[8][2];
#pragma unroll
            for (int nt = 0; nt < 8; nt++) {
                int n = nh * 64 + nt * 8 + g;
                bf[nt][0] = pack_h2(bk0[n],                  bk0[LS_STRIDE + n]);
                bf[nt][1] = pack_h2(bk0[8 * LS_STRIDE + n],  bk0[9 * LS_STRIDE + n]);
            }
#pragma unroll
            for (int mt = 0; mt < 2; mt++)
#pragma unroll
                for (int nt = 0; nt < 8; nt++)
                    MMA_F16(acca[mt][nt], af[mt], bf[nt]);
        }
#pragma unroll
        for (int mt = 0; mt < 2; mt++) {
            int c = m0w + mt * 16 + g;
            float* r0 = aug + (size_t)c * HW + nh * 64 + 2 * tg;
            float* r1 = r0 + (size_t)8 * HW;
#pragma unroll
            for (int nt = 0; nt < 8; nt++) {
                *(float2*)(r0 + nt * 8) = make_float2(acca[mt][nt][0], acca[mt][nt][1]);
                *(float2*)(r1 + nt * 8) = make_float2(acca[mt][nt][2], acca[mt][nt][3]);
            }
        }
    }
#undef AT_LOAD
}

// ---------------- launch --------------------------------------------------
extern "C" void kernel_launch(void* const* d_in, const int* in_sizes, int n_in,
                              void* d_out, int out_size) {
    const float* feats = (const float*)d_in[0];
    const float* preds = (const float*)d_in[1];
    const float* W     = (const float*)d_in[2];
    const float* bias  = (const float*)d_in[3];
    const int*   epoch = (const int*)d_in[4];
    float* out = (float*)d_out;

    cudaFuncSetAttribute(proj_mma, cudaFuncAttributeMaxDynamicSharedMemorySize, SMEM_TOTAL);
    cudaFuncSetAttribute(attn_mma, cudaFuncAttributeMaxDynamicSharedMemorySize, AT_SMEM_TOTAL);

    proj_mma<<<dim3(NXT, COUT / BM, BATCH), NTHREADS, SMEM_TOTAL>>>(feats, preds, W, bias, out);
    pooled_kernel<<<BATCH, 1024>>>(preds, W, bias);
    gram_kernel<<<32, 256>>>();
    scan_kernel<<<1, 32>>>(epoch);
    recon_kernel<<<32, 256>>>();
    attn_mma<<<dim3(HW / AT_L, BATCH), 256, AT_SMEM_TOTAL>>>(out);
}